// round 2
// baseline (speedup 1.0000x reference)
#include <cuda_runtime.h>
#include <math.h>

#define MAXN 50000
#define MAXE 800000
#define DIM 128
#define NH 8
#define HC 16

// ---------------- scratch (static device globals; no allocation) ------------
__device__ float g_h[MAXN * DIM];        // h = x @ W
__device__ float g_as[MAXN * NH];        // per-node att_src dot
__device__ float g_ad[MAXN * NH];        // per-node att_dst dot
__device__ float g_selfw[MAXN * NH];     // self-loop exp weight
__device__ float g_denom[MAXN * NH];     // softmax denominator per (dst, head)
__device__ float g_w[MAXE * NH];         // per-edge exp weights (0 for src==dst)
__device__ float g_agg[MAXN * DIM];      // edge aggregation -> becomes GAT output y
__device__ float g_deg[MAXN];
__device__ float g_di[MAXN];             // rsqrt(deg + eps)
__device__ float g_r[MAXN];              // rowmean(y)
__device__ float g_mean[MAXN];           // laplacian mean
__device__ float g_q[MAXN];              // mean_k (y - mean)^2
__device__ float g_var[MAXN];            // laplacian var
__device__ float g_ln[MAXN * DIM];       // after LayerNorm (MLP input + residual)
__device__ float g_t[MAXN * 2 * DIM];    // GELU intermediate
__device__ float g_z[MAXN * DIM];        // MLP out + residual

// ---------------- init ------------------------------------------------------
__global__ void k_init(int N) {
    int i = blockIdx.x * blockDim.x + threadIdx.x;
    if (i < N * DIM) g_agg[i] = 0.f;
    if (i < N * NH) g_denom[i] = 0.f;
    if (i < N) { g_deg[i] = 0.f; g_mean[i] = 0.f; g_var[i] = 0.f; }
}

// ---------------- generic tiled fp32 GEMM -----------------------------------
__device__ __forceinline__ float gelu_exact(float v) {
    return 0.5f * v * (1.0f + erff(v * 0.7071067811865476f));
}

// ACT: 0 = bias only, 1 = bias + exact GELU, 2 = bias + residual add
template <int ACT>
__global__ void k_gemm(int M, int N, int K,
                       const float* __restrict__ A, const float* __restrict__ B,
                       const float* __restrict__ bias, const float* __restrict__ res,
                       float* __restrict__ Cout) {
    const int BM = 64, BN = 64, BK = 16, TM = 4, TN = 4;
    __shared__ float As[BK][BM];
    __shared__ float Bs[BK][BN];
    int tid = threadIdx.x;
    int row0 = blockIdx.y * BM, col0 = blockIdx.x * BN;
    float acc[TM][TN];
#pragma unroll
    for (int i = 0; i < TM; i++)
#pragma unroll
        for (int j = 0; j < TN; j++) acc[i][j] = 0.f;
    int tr = (tid / 16) * TM, tc = (tid % 16) * TN;

    for (int k0 = 0; k0 < K; k0 += BK) {
#pragma unroll
        for (int i = tid; i < BM * BK; i += 256) {
            int r = i / BK, c = i % BK;
            As[c][r] = (row0 + r < M) ? A[(size_t)(row0 + r) * K + k0 + c] : 0.f;
        }
#pragma unroll
        for (int i = tid; i < BK * BN; i += 256) {
            int r = i / BN, c = i % BN;
            Bs[r][c] = B[(size_t)(k0 + r) * N + col0 + c];
        }
        __syncthreads();
#pragma unroll
        for (int k = 0; k < BK; k++) {
            float a[TM], b[TN];
#pragma unroll
            for (int i = 0; i < TM; i++) a[i] = As[k][tr + i];
#pragma unroll
            for (int j = 0; j < TN; j++) b[j] = Bs[k][tc + j];
#pragma unroll
            for (int i = 0; i < TM; i++)
#pragma unroll
                for (int j = 0; j < TN; j++) acc[i][j] += a[i] * b[j];
        }
        __syncthreads();
    }
#pragma unroll
    for (int i = 0; i < TM; i++) {
        int r = row0 + tr + i;
        if (r >= M) continue;
#pragma unroll
        for (int j = 0; j < TN; j++) {
            int c = col0 + tc + j;
            float v = acc[i][j] + (bias ? bias[c] : 0.f);
            if (ACT == 1) v = gelu_exact(v);
            if (ACT == 2) v += res[(size_t)r * N + c];
            Cout[(size_t)r * N + c] = v;
        }
    }
}

// ---------------- attention scalars -----------------------------------------
__global__ void k_attn(int N, const float* __restrict__ att_src,
                       const float* __restrict__ att_dst) {
    int i = blockIdx.x * blockDim.x + threadIdx.x;  // (n, h)
    if (i >= N * NH) return;
    int n = i >> 3, h = i & 7;
    const float* hp = &g_h[n * DIM + h * HC];
    float s = 0.f, d = 0.f;
#pragma unroll
    for (int c = 0; c < HC; c++) {
        float v = hp[c];
        s += v * __ldg(&att_src[h * HC + c]);
        d += v * __ldg(&att_dst[h * HC + c]);
    }
    g_as[i] = s;
    g_ad[i] = d;
}

// ---------------- edge pass 1: exp weights + denom + degree -----------------
__global__ void k_edge1(const int* __restrict__ ei, int E) {
    int e = blockIdx.x * blockDim.x + threadIdx.x;
    if (e >= E) return;
    int s = ei[e], d = ei[E + e];
    atomicAdd(&g_deg[s], 1.0f);
    float4 as0 = ((const float4*)g_as)[s * 2], as1 = ((const float4*)g_as)[s * 2 + 1];
    float4 ad0 = ((const float4*)g_ad)[d * 2], ad1 = ((const float4*)g_ad)[d * 2 + 1];
    float l[8] = {as0.x + ad0.x, as0.y + ad0.y, as0.z + ad0.z, as0.w + ad0.w,
                  as1.x + ad1.x, as1.y + ad1.y, as1.z + ad1.z, as1.w + ad1.w};
    bool self = (s == d);
#pragma unroll
    for (int h = 0; h < 8; h++) {
        float v = l[h];
        v = v > 0.f ? v : 0.2f * v;
        float w = self ? 0.f : expf(v);
        g_w[(size_t)e * 8 + h] = w;
        if (!self) atomicAdd(&g_denom[d * 8 + h], w);
    }
}

// ---------------- self loops ------------------------------------------------
__global__ void k_self(int N) {
    int i = blockIdx.x * blockDim.x + threadIdx.x;
    if (i >= N * NH) return;
    float v = g_as[i] + g_ad[i];
    v = v > 0.f ? v : 0.2f * v;
    float e = expf(v);
    g_selfw[i] = e;
    g_denom[i] += e;  // runs after k_edge1, unique per thread
}

// ---------------- edge aggregation (warp per edge) --------------------------
__global__ void k_agg(const int* __restrict__ ei, int E) {
    int gid = blockIdx.x * blockDim.x + threadIdx.x;
    int e = gid >> 5;
    if (e >= E) return;
    int lane = gid & 31;
    int s = ei[e], d = ei[E + e];
    float w = g_w[(size_t)e * 8 + (lane >> 2)];
    if (w == 0.f) return;
    float4 hv = ((const float4*)g_h)[(size_t)s * 32 + lane];
    float* dst = &g_agg[(size_t)d * DIM + lane * 4];
    atomicAdd(dst + 0, w * hv.x);
    atomicAdd(dst + 1, w * hv.y);
    atomicAdd(dst + 2, w * hv.z);
    atomicAdd(dst + 3, w * hv.w);
}

// ---------------- GAT finalize: y, rowmean, di ------------------------------
__global__ void k_gatfin(int N, const float* __restrict__ gat_bias) {
    int gid = blockIdx.x * blockDim.x + threadIdx.x;
    int n = gid >> 5;
    if (n >= N) return;
    int lane = gid & 31;
    int h = lane >> 2;
    float dn = g_denom[n * 8 + h] + 1e-16f;
    float sw = g_selfw[n * 8 + h];
    float4 a = ((const float4*)g_agg)[n * 32 + lane];
    float4 hv = ((const float4*)g_h)[n * 32 + lane];
    float4 b = ((const float4*)gat_bias)[lane];
    float4 y;
    y.x = (a.x + sw * hv.x) / dn + b.x;
    y.y = (a.y + sw * hv.y) / dn + b.y;
    y.z = (a.z + sw * hv.z) / dn + b.z;
    y.w = (a.w + sw * hv.w) / dn + b.w;
    ((float4*)g_agg)[n * 32 + lane] = y;
    float sum = y.x + y.y + y.z + y.w;
#pragma unroll
    for (int o = 16; o > 0; o >>= 1) sum += __shfl_xor_sync(0xffffffffu, sum, o);
    if (lane == 0) {
        g_r[n] = sum * (1.f / 128.f);
        g_di[n] = rsqrtf(g_deg[n] + 1e-6f);
    }
}

// ---------------- laplacian mean (scalar per edge) --------------------------
__global__ void k_edge_mean(const int* __restrict__ ei, int E) {
    int e = blockIdx.x * blockDim.x + threadIdx.x;
    if (e >= E) return;
    int s = ei[e], d = ei[E + e];
    atomicAdd(&g_mean[s], g_di[s] * g_di[d] * g_r[d]);
}

// ---------------- per-node q ------------------------------------------------
__global__ void k_q(int N) {
    int gid = blockIdx.x * blockDim.x + threadIdx.x;
    int n = gid >> 5;
    if (n >= N) return;
    int lane = gid & 31;
    float m = g_mean[n];
    float4 y = ((const float4*)g_agg)[n * 32 + lane];
    float a0 = y.x - m, a1 = y.y - m, a2 = y.z - m, a3 = y.w - m;
    float s = a0 * a0 + a1 * a1 + a2 * a2 + a3 * a3;
#pragma unroll
    for (int o = 16; o > 0; o >>= 1) s += __shfl_xor_sync(0xffffffffu, s, o);
    if (lane == 0) g_q[n] = s * (1.f / 128.f);
}

// ---------------- laplacian var (scalar per edge) ---------------------------
__global__ void k_edge_var(const int* __restrict__ ei, int E) {
    int e = blockIdx.x * blockDim.x + threadIdx.x;
    if (e >= E) return;
    int s = ei[e], d = ei[E + e];
    atomicAdd(&g_var[s], g_di[s] * g_di[d] * g_q[d]);
}

// ---------------- laplacian norm + residual + LayerNorm ---------------------
__global__ void k_lnfuse(int N, const float* __restrict__ x,
                         const float* __restrict__ s1, const float* __restrict__ b1,
                         const float* __restrict__ s2, const float* __restrict__ b2) {
    int gid = blockIdx.x * blockDim.x + threadIdx.x;
    int n = gid >> 5;
    if (n >= N) return;
    int lane = gid & 31;
    float m = g_mean[n];
    float inv1 = 1.f / sqrtf(g_var[n] + 1e-6f);
    float4 y = ((const float4*)g_agg)[n * 32 + lane];
    float4 xv = ((const float4*)x)[(size_t)n * 32 + lane];
    float4 sc1 = ((const float4*)s1)[lane];
    float4 bb1 = ((const float4*)b1)[lane];
    float4 sc2 = ((const float4*)s2)[lane];
    float4 bb2 = ((const float4*)b2)[lane];
    float o0 = (y.x - m) * inv1 * sc1.x + bb1.x + xv.x;
    float o1 = (y.y - m) * inv1 * sc1.y + bb1.y + xv.y;
    float o2 = (y.z - m) * inv1 * sc1.z + bb1.z + xv.z;
    float o3 = (y.w - m) * inv1 * sc1.w + bb1.w + xv.w;
    float sum = o0 + o1 + o2 + o3;
#pragma unroll
    for (int o = 16; o > 0; o >>= 1) sum += __shfl_xor_sync(0xffffffffu, sum, o);
    float mu = sum * (1.f / 128.f);
    float c0 = o0 - mu, c1 = o1 - mu, c2 = o2 - mu, c3 = o3 - mu;
    float vs = c0 * c0 + c1 * c1 + c2 * c2 + c3 * c3;
#pragma unroll
    for (int o = 16; o > 0; o >>= 1) vs += __shfl_xor_sync(0xffffffffu, vs, o);
    float inv2 = rsqrtf(vs * (1.f / 128.f) + 1e-5f);
    float4 r;
    r.x = c0 * inv2 * sc2.x + bb2.x;
    r.y = c1 * inv2 * sc2.y + bb2.y;
    r.z = c2 * inv2 * sc2.z + bb2.z;
    r.w = c3 * inv2 * sc2.w + bb2.w;
    ((float4*)g_ln)[n * 32 + lane] = r;
}

// ---------------- final L2 normalize ----------------------------------------
__global__ void k_l2norm(int N, float* __restrict__ out) {
    int gid = blockIdx.x * blockDim.x + threadIdx.x;
    int n = gid >> 5;
    if (n >= N) return;
    int lane = gid & 31;
    float4 z = ((const float4*)g_z)[n * 32 + lane];
    float s = z.x * z.x + z.y * z.y + z.z * z.z + z.w * z.w;
#pragma unroll
    for (int o = 16; o > 0; o >>= 1) s += __shfl_xor_sync(0xffffffffu, s, o);
    float inv = 1.f / fmaxf(sqrtf(s), 1e-12f);
    float4 r;
    r.x = z.x * inv; r.y = z.y * inv; r.z = z.z * inv; r.w = z.w * inv;
    ((float4*)out)[(size_t)n * 32 + lane] = r;
}

// ---------------- launch ----------------------------------------------------
extern "C" void kernel_launch(void* const* d_in, const int* in_sizes, int n_in,
                              void* d_out, int out_size) {
    const float* x        = (const float*)d_in[0];
    const int* ei         = (const int*)d_in[1];
    const float* W        = (const float*)d_in[2];
    const float* att_src  = (const float*)d_in[3];
    const float* att_dst  = (const float*)d_in[4];
    const float* gat_bias = (const float*)d_in[5];
    const float* ln1s     = (const float*)d_in[6];
    const float* ln1b     = (const float*)d_in[7];
    const float* ln2s     = (const float*)d_in[8];
    const float* ln2b     = (const float*)d_in[9];
    const float* W1       = (const float*)d_in[10];
    const float* b1       = (const float*)d_in[11];
    const float* W2       = (const float*)d_in[12];
    const float* b2       = (const float*)d_in[13];
    float* out            = (float*)d_out;

    int N = in_sizes[0] / DIM;
    int E = in_sizes[1] / 2;

    float *p_h, *p_ln, *p_t, *p_z;
    cudaGetSymbolAddress((void**)&p_h, g_h);
    cudaGetSymbolAddress((void**)&p_ln, g_ln);
    cudaGetSymbolAddress((void**)&p_t, g_t);
    cudaGetSymbolAddress((void**)&p_z, g_z);

    // init scratch
    k_init<<<(N * DIM + 255) / 256, 256>>>(N);

    // h = x @ W
    k_gemm<0><<<dim3(DIM / 64, (N + 63) / 64), 256>>>(N, DIM, DIM, x, W, nullptr, nullptr, p_h);

    // attention scalars
    k_attn<<<(N * NH + 255) / 256, 256>>>(N, att_src, att_dst);

    // edge softmax weights + denominators + degree
    k_edge1<<<(E + 255) / 256, 256>>>(ei, E);
    k_self<<<(N * NH + 255) / 256, 256>>>(N);

    // aggregation
    k_agg<<<(E * 32 + 255) / 256, 256>>>(ei, E);

    // finalize GAT output, rowmean, di
    k_gatfin<<<(N * 32 + 255) / 256, 256>>>(N, gat_bias);

    // laplacian norm (scalar edge passes)
    k_edge_mean<<<(E + 255) / 256, 256>>>(ei, E);
    k_q<<<(N * 32 + 255) / 256, 256>>>(N);
    k_edge_var<<<(E + 255) / 256, 256>>>(ei, E);

    // laplacian norm + residual + LayerNorm
    k_lnfuse<<<(N * 32 + 255) / 256, 256>>>(N, x, ln1s, ln1b, ln2s, ln2b);

    // MLP
    k_gemm<1><<<dim3(2 * DIM / 64, (N + 63) / 64), 256>>>(N, 2 * DIM, DIM, p_ln, W1, b1, nullptr, p_t);
    k_gemm<2><<<dim3(DIM / 64, (N + 63) / 64), 256>>>(N, DIM, 2 * DIM, p_t, W2, b2, p_ln, p_z);

    // final row-wise L2 normalize
    k_l2norm<<<(N * 32 + 255) / 256, 256>>>(N, out);
}

// round 3
// speedup vs baseline: 2.2276x; 2.2276x over previous
#include <cuda_runtime.h>
#include <math.h>

#define MAXN 50000
#define MAXE 800000
#define DIM 128
#define NH 8
#define HC 16

// ---------------- scratch (static device globals; no allocation) ------------
__device__ float g_h[MAXN * DIM];        // h = x @ W
__device__ float g_as[MAXN * NH];        // per-node att_src dot
__device__ float g_ad[MAXN * NH];        // per-node att_dst dot
__device__ float g_denom[MAXN * NH];     // softmax denominator per (dst, head)
__device__ float g_w[MAXE * NH];         // per-edge exp weights (0 for src==dst)
__device__ float g_agg[MAXN * DIM];      // edge aggregation -> GAT output y
__device__ float g_deg[MAXN];
__device__ float g_di[MAXN];             // rsqrt(deg + eps)
__device__ float g_r[MAXN];              // rowmean(y)
__device__ float g_mean[MAXN];           // laplacian mean
__device__ float g_q[MAXN];              // mean_k (y - mean)^2
__device__ float g_var[MAXN];            // laplacian var
__device__ float g_ln[MAXN * DIM];       // after LayerNorm (MLP input + residual)
__device__ float g_t[MAXN * 2 * DIM];    // GELU intermediate
__device__ float g_z[MAXN * DIM];        // MLP out + residual

// ---------------- helpers ---------------------------------------------------
__device__ __forceinline__ unsigned f2tf32(float v) {
    unsigned r;
    asm("cvt.rna.tf32.f32 %0, %1;" : "=r"(r) : "f"(v));
    return r;
}

__device__ __forceinline__ void red_add_v4(float* p, float a, float b, float c, float d) {
    asm volatile("red.global.add.v4.f32 [%0], {%1, %2, %3, %4};"
                 :: "l"(p), "f"(a), "f"(b), "f"(c), "f"(d) : "memory");
}

__device__ __forceinline__ float gelu_exact(float v) {
    return 0.5f * v * (1.0f + erff(v * 0.7071067811865476f));
}

// ---------------- init ------------------------------------------------------
__global__ void k_init(int N) {
    int i = blockIdx.x * blockDim.x + threadIdx.x;
    if (i < N * DIM) g_agg[i] = 0.f;
    if (i < N * NH) g_denom[i] = 0.f;
    if (i < N) { g_deg[i] = 0.f; g_mean[i] = 0.f; g_var[i] = 0.f; }
}

// ---------------- tf32 tensor-core GEMM (C = A @ B, row-major) --------------
// Tile 128x128xK, BK=32, 256 threads = 8 warps (4 m x 2 n), warp tile 32x64.
// ACT: 0 = none, 1 = bias + exact GELU, 2 = bias + residual add
template <int ACT>
__global__ __launch_bounds__(256) void k_gemm_tc(
        int M, int N, int K,
        const float* __restrict__ A, const float* __restrict__ B,
        const float* __restrict__ bias, const float* __restrict__ res,
        float* __restrict__ Cout) {
    const int SA = 36;    // A smem row stride (floats): bank-conflict-free frag reads
    const int SB = 136;   // B smem row stride
    __shared__ unsigned sA[128 * SA];
    __shared__ unsigned sB[32 * SB];

    int tid = threadIdx.x;
    int row0 = blockIdx.y * 128, col0 = blockIdx.x * 128;
    int wid = tid >> 5, lane = tid & 31;
    int wm = wid & 3, wn = wid >> 2;       // warp tile coords
    int t4r = lane >> 2, t4c = lane & 3;   // quad row / col

    float acc[2][8][4];
#pragma unroll
    for (int mt = 0; mt < 2; mt++)
#pragma unroll
        for (int nt = 0; nt < 8; nt++)
#pragma unroll
            for (int i = 0; i < 4; i++) acc[mt][nt][i] = 0.f;

    for (int k0 = 0; k0 < K; k0 += 32) {
        // load A tile 128x32 (float4, tf32-converted)
#pragma unroll
        for (int j = 0; j < 4; j++) {
            int i = tid + j * 256;
            int r = i >> 3, c4 = (i & 7) * 4;
            float4 v = make_float4(0.f, 0.f, 0.f, 0.f);
            if (row0 + r < M)
                v = *(const float4*)&A[(size_t)(row0 + r) * K + k0 + c4];
            uint4 u = {f2tf32(v.x), f2tf32(v.y), f2tf32(v.z), f2tf32(v.w)};
            *(uint4*)&sA[r * SA + c4] = u;
        }
        // load B tile 32x128
#pragma unroll
        for (int j = 0; j < 4; j++) {
            int i = tid + j * 256;
            int r = i >> 5, c4 = (i & 31) * 4;
            float4 v = *(const float4*)&B[(size_t)(k0 + r) * N + col0 + c4];
            uint4 u = {f2tf32(v.x), f2tf32(v.y), f2tf32(v.z), f2tf32(v.w)};
            *(uint4*)&sB[r * SB + c4] = u;
        }
        __syncthreads();

#pragma unroll
        for (int kk = 0; kk < 32; kk += 8) {
            unsigned a[2][4];
#pragma unroll
            for (int mt = 0; mt < 2; mt++) {
                int r = wm * 32 + mt * 16 + t4r;
                a[mt][0] = sA[r * SA + kk + t4c];
                a[mt][1] = sA[(r + 8) * SA + kk + t4c];
                a[mt][2] = sA[r * SA + kk + t4c + 4];
                a[mt][3] = sA[(r + 8) * SA + kk + t4c + 4];
            }
#pragma unroll
            for (int nt = 0; nt < 8; nt++) {
                int n = wn * 64 + nt * 8 + t4r;
                unsigned b0 = sB[(kk + t4c) * SB + n];
                unsigned b1 = sB[(kk + t4c + 4) * SB + n];
#pragma unroll
                for (int mt = 0; mt < 2; mt++) {
                    asm volatile(
                        "mma.sync.aligned.m16n8k8.row.col.f32.tf32.tf32.f32 "
                        "{%0,%1,%2,%3}, {%4,%5,%6,%7}, {%8,%9}, {%0,%1,%2,%3};"
                        : "+f"(acc[mt][nt][0]), "+f"(acc[mt][nt][1]),
                          "+f"(acc[mt][nt][2]), "+f"(acc[mt][nt][3])
                        : "r"(a[mt][0]), "r"(a[mt][1]), "r"(a[mt][2]), "r"(a[mt][3]),
                          "r"(b0), "r"(b1));
                }
            }
        }
        __syncthreads();
    }

    // epilogue
#pragma unroll
    for (int mt = 0; mt < 2; mt++) {
#pragma unroll
        for (int nt = 0; nt < 8; nt++) {
            int c = col0 + wn * 64 + nt * 8 + 2 * t4c;
            float bb0 = bias ? bias[c] : 0.f;
            float bb1 = bias ? bias[c + 1] : 0.f;
#pragma unroll
            for (int half = 0; half < 2; half++) {
                int r = row0 + wm * 32 + mt * 16 + t4r + half * 8;
                if (r >= M) continue;
                float v0 = acc[mt][nt][half * 2 + 0] + bb0;
                float v1 = acc[mt][nt][half * 2 + 1] + bb1;
                if (ACT == 1) { v0 = gelu_exact(v0); v1 = gelu_exact(v1); }
                if (ACT == 2) {
                    float2 rv = *(const float2*)&res[(size_t)r * N + c];
                    v0 += rv.x; v1 += rv.y;
                }
                float2 o = {v0, v1};
                *(float2*)&Cout[(size_t)r * N + c] = o;
            }
        }
    }
}

// ---------------- attention scalars -----------------------------------------
__global__ void k_attn(int N, const float* __restrict__ att_src,
                       const float* __restrict__ att_dst) {
    int i = blockIdx.x * blockDim.x + threadIdx.x;  // (n, h)
    if (i >= N * NH) return;
    int n = i >> 3, h = i & 7;
    const float* hp = &g_h[n * DIM + h * HC];
    float s = 0.f, d = 0.f;
#pragma unroll
    for (int c = 0; c < HC; c++) {
        float v = hp[c];
        s += v * __ldg(&att_src[h * HC + c]);
        d += v * __ldg(&att_dst[h * HC + c]);
    }
    g_as[i] = s;
    g_ad[i] = d;
}

// ---------------- edge pass 1: exp weights + denom + degree -----------------
__global__ void k_edge1(const int* __restrict__ ei, int E) {
    int e = blockIdx.x * blockDim.x + threadIdx.x;
    if (e >= E) return;
    int s = ei[e], d = ei[E + e];
    atomicAdd(&g_deg[s], 1.0f);
    float4 as0 = ((const float4*)g_as)[s * 2], as1 = ((const float4*)g_as)[s * 2 + 1];
    float4 ad0 = ((const float4*)g_ad)[d * 2], ad1 = ((const float4*)g_ad)[d * 2 + 1];
    float l[8] = {as0.x + ad0.x, as0.y + ad0.y, as0.z + ad0.z, as0.w + ad0.w,
                  as1.x + ad1.x, as1.y + ad1.y, as1.z + ad1.z, as1.w + ad1.w};
    bool self = (s == d);
    float w[8];
#pragma unroll
    for (int h = 0; h < 8; h++) {
        float v = l[h];
        v = v > 0.f ? v : 0.2f * v;
        w[h] = self ? 0.f : expf(v);
        g_w[(size_t)e * 8 + h] = w[h];
    }
    if (!self) {
        red_add_v4(&g_denom[d * 8], w[0], w[1], w[2], w[3]);
        red_add_v4(&g_denom[d * 8 + 4], w[4], w[5], w[6], w[7]);
    }
}

// ---------------- edge aggregation (warp per edge, red.v4) ------------------
__global__ void k_agg(const int* __restrict__ ei, int E) {
    int gid = blockIdx.x * blockDim.x + threadIdx.x;
    int e = gid >> 5;
    if (e >= E) return;
    int lane = gid & 31;
    int s = ei[e], d = ei[E + e];
    float w = g_w[(size_t)e * 8 + (lane >> 2)];
    if (w == 0.f) return;
    float4 hv = ((const float4*)g_h)[(size_t)s * 32 + lane];
    red_add_v4(&g_agg[(size_t)d * DIM + lane * 4],
               w * hv.x, w * hv.y, w * hv.z, w * hv.w);
}

// ---------------- GAT finalize: y (incl. self loop), rowmean, di ------------
__global__ void k_gatfin(int N, const float* __restrict__ gat_bias) {
    int gid = blockIdx.x * blockDim.x + threadIdx.x;
    int n = gid >> 5;
    if (n >= N) return;
    int lane = gid & 31;
    int h = lane >> 2;
    // self-loop weight recomputed locally
    float v = g_as[n * 8 + h] + g_ad[n * 8 + h];
    v = v > 0.f ? v : 0.2f * v;
    float sw = expf(v);
    float dn = g_denom[n * 8 + h] + sw + 1e-16f;
    float4 a = ((const float4*)g_agg)[n * 32 + lane];
    float4 hv = ((const float4*)g_h)[n * 32 + lane];
    float4 b = ((const float4*)gat_bias)[lane];
    float4 y;
    y.x = (a.x + sw * hv.x) / dn + b.x;
    y.y = (a.y + sw * hv.y) / dn + b.y;
    y.z = (a.z + sw * hv.z) / dn + b.z;
    y.w = (a.w + sw * hv.w) / dn + b.w;
    ((float4*)g_agg)[n * 32 + lane] = y;
    float sum = y.x + y.y + y.z + y.w;
#pragma unroll
    for (int o = 16; o > 0; o >>= 1) sum += __shfl_xor_sync(0xffffffffu, sum, o);
    if (lane == 0) {
        g_r[n] = sum * (1.f / 128.f);
        g_di[n] = rsqrtf(g_deg[n] + 1e-6f);
    }
}

// ---------------- laplacian mean (scalar per edge) --------------------------
__global__ void k_edge_mean(const int* __restrict__ ei, int E) {
    int e = blockIdx.x * blockDim.x + threadIdx.x;
    if (e >= E) return;
    int s = ei[e], d = ei[E + e];
    atomicAdd(&g_mean[s], g_di[s] * g_di[d] * g_r[d]);
}

// ---------------- per-node q ------------------------------------------------
__global__ void k_q(int N) {
    int gid = blockIdx.x * blockDim.x + threadIdx.x;
    int n = gid >> 5;
    if (n >= N) return;
    int lane = gid & 31;
    float m = g_mean[n];
    float4 y = ((const float4*)g_agg)[n * 32 + lane];
    float a0 = y.x - m, a1 = y.y - m, a2 = y.z - m, a3 = y.w - m;
    float s = a0 * a0 + a1 * a1 + a2 * a2 + a3 * a3;
#pragma unroll
    for (int o = 16; o > 0; o >>= 1) s += __shfl_xor_sync(0xffffffffu, s, o);
    if (lane == 0) g_q[n] = s * (1.f / 128.f);
}

// ---------------- laplacian var (scalar per edge) ---------------------------
__global__ void k_edge_var(const int* __restrict__ ei, int E) {
    int e = blockIdx.x * blockDim.x + threadIdx.x;
    if (e >= E) return;
    int s = ei[e], d = ei[E + e];
    atomicAdd(&g_var[s], g_di[s] * g_di[d] * g_q[d]);
}

// ---------------- laplacian norm + residual + LayerNorm ---------------------
__global__ void k_lnfuse(int N, const float* __restrict__ x,
                         const float* __restrict__ s1, const float* __restrict__ b1,
                         const float* __restrict__ s2, const float* __restrict__ b2) {
    int gid = blockIdx.x * blockDim.x + threadIdx.x;
    int n = gid >> 5;
    if (n >= N) return;
    int lane = gid & 31;
    float m = g_mean[n];
    float inv1 = 1.f / sqrtf(g_var[n] + 1e-6f);
    float4 y = ((const float4*)g_agg)[n * 32 + lane];
    float4 xv = ((const float4*)x)[(size_t)n * 32 + lane];
    float4 sc1 = ((const float4*)s1)[lane];
    float4 bb1 = ((const float4*)b1)[lane];
    float4 sc2 = ((const float4*)s2)[lane];
    float4 bb2 = ((const float4*)b2)[lane];
    float o0 = (y.x - m) * inv1 * sc1.x + bb1.x + xv.x;
    float o1 = (y.y - m) * inv1 * sc1.y + bb1.y + xv.y;
    float o2 = (y.z - m) * inv1 * sc1.z + bb1.z + xv.z;
    float o3 = (y.w - m) * inv1 * sc1.w + bb1.w + xv.w;
    float sum = o0 + o1 + o2 + o3;
#pragma unroll
    for (int o = 16; o > 0; o >>= 1) sum += __shfl_xor_sync(0xffffffffu, sum, o);
    float mu = sum * (1.f / 128.f);
    float c0 = o0 - mu, c1 = o1 - mu, c2 = o2 - mu, c3 = o3 - mu;
    float vs = c0 * c0 + c1 * c1 + c2 * c2 + c3 * c3;
#pragma unroll
    for (int o = 16; o > 0; o >>= 1) vs += __shfl_xor_sync(0xffffffffu, vs, o);
    float inv2 = rsqrtf(vs * (1.f / 128.f) + 1e-5f);
    float4 r;
    r.x = c0 * inv2 * sc2.x + bb2.x;
    r.y = c1 * inv2 * sc2.y + bb2.y;
    r.z = c2 * inv2 * sc2.z + bb2.z;
    r.w = c3 * inv2 * sc2.w + bb2.w;
    ((float4*)g_ln)[n * 32 + lane] = r;
}

// ---------------- final L2 normalize ----------------------------------------
__global__ void k_l2norm(int N, float* __restrict__ out) {
    int gid = blockIdx.x * blockDim.x + threadIdx.x;
    int n = gid >> 5;
    if (n >= N) return;
    int lane = gid & 31;
    float4 z = ((const float4*)g_z)[n * 32 + lane];
    float s = z.x * z.x + z.y * z.y + z.z * z.z + z.w * z.w;
#pragma unroll
    for (int o = 16; o > 0; o >>= 1) s += __shfl_xor_sync(0xffffffffu, s, o);
    float inv = 1.f / fmaxf(sqrtf(s), 1e-12f);
    float4 r;
    r.x = z.x * inv; r.y = z.y * inv; r.z = z.z * inv; r.w = z.w * inv;
    ((float4*)out)[(size_t)n * 32 + lane] = r;
}

// ---------------- launch ----------------------------------------------------
extern "C" void kernel_launch(void* const* d_in, const int* in_sizes, int n_in,
                              void* d_out, int out_size) {
    const float* x        = (const float*)d_in[0];
    const int* ei         = (const int*)d_in[1];
    const float* W        = (const float*)d_in[2];
    const float* att_src  = (const float*)d_in[3];
    const float* att_dst  = (const float*)d_in[4];
    const float* gat_bias = (const float*)d_in[5];
    const float* ln1s     = (const float*)d_in[6];
    const float* ln1b     = (const float*)d_in[7];
    const float* ln2s     = (const float*)d_in[8];
    const float* ln2b     = (const float*)d_in[9];
    const float* W1       = (const float*)d_in[10];
    const float* b1       = (const float*)d_in[11];
    const float* W2       = (const float*)d_in[12];
    const float* b2       = (const float*)d_in[13];
    float* out            = (float*)d_out;

    int N = in_sizes[0] / DIM;
    int E = in_sizes[1] / 2;

    float *p_h, *p_ln, *p_t, *p_z;
    cudaGetSymbolAddress((void**)&p_h, g_h);
    cudaGetSymbolAddress((void**)&p_ln, g_ln);
    cudaGetSymbolAddress((void**)&p_t, g_t);
    cudaGetSymbolAddress((void**)&p_z, g_z);

    int mb = (N + 127) / 128;

    // init scratch
    k_init<<<(N * DIM + 255) / 256, 256>>>(N);

    // h = x @ W  (tf32 TC)
    k_gemm_tc<0><<<dim3(1, mb), 256>>>(N, DIM, DIM, x, W, nullptr, nullptr, p_h);

    // attention scalars
    k_attn<<<(N * NH + 255) / 256, 256>>>(N, att_src, att_dst);

    // edge softmax weights + denominators + degree
    k_edge1<<<(E + 255) / 256, 256>>>(ei, E);

    // aggregation
    k_agg<<<(E * 32 + 255) / 256, 256>>>(ei, E);

    // finalize GAT output (incl. self loop), rowmean, di
    k_gatfin<<<(N * 32 + 255) / 256, 256>>>(N, gat_bias);

    // laplacian norm (scalar edge passes)
    k_edge_mean<<<(E + 255) / 256, 256>>>(ei, E);
    k_q<<<(N * 32 + 255) / 256, 256>>>(N);
    k_edge_var<<<(E + 255) / 256, 256>>>(ei, E);

    // laplacian norm + residual + LayerNorm
    k_lnfuse<<<(N * 32 + 255) / 256, 256>>>(N, x, ln1s, ln1b, ln2s, ln2b);

    // MLP (tf32 TC)
    k_gemm_tc<1><<<dim3(2, mb), 256>>>(N, 2 * DIM, DIM, p_ln, W1, b1, nullptr, p_t);
    k_gemm_tc<2><<<dim3(1, mb), 256>>>(N, DIM, 2 * DIM, p_t, W2, b2, p_ln, p_z);

    // final row-wise L2 normalize
    k_l2norm<<<(N * 32 + 255) / 256, 256>>>(N, out);
}

// round 4
// speedup vs baseline: 3.2243x; 1.4474x over previous
#include <cuda_runtime.h>
#include <math.h>

#define MAXN 50000
#define MAXE 800000
#define DIM 128
#define NH 8
#define HC 16
#define SCANB 1024
#define MAXBLK 64

// ---------------- scratch (static device globals; no allocation) ------------
__device__ float g_h[MAXN * DIM];        // h = x @ W
__device__ float g_as[MAXN * NH];        // per-node att_src dot
__device__ float g_ad[MAXN * NH];        // per-node att_dst dot
__device__ float g_agg[MAXN * DIM];      // GAT output y
__device__ float g_deg[MAXN];            // out-degree (float)
__device__ float g_di[MAXN];             // rsqrt(deg + eps)
__device__ float g_r[MAXN];              // rowmean(y)
__device__ float g_mean[MAXN];           // laplacian mean
__device__ float g_q[MAXN];              // mean_k (y - mean)^2
__device__ float g_var[MAXN];            // laplacian var
__device__ float g_ln[MAXN * DIM];       // after LayerNorm (MLP input + residual)
__device__ float g_t[MAXN * 2 * DIM];    // GELU intermediate
__device__ float g_z[MAXN * DIM];        // MLP out + residual
__device__ int   g_indeg[MAXN];          // in-degree histogram
__device__ int   g_cursor[MAXN];         // scatter cursors
__device__ int   g_off[MAXN];            // CSR offsets (by dst)
__device__ int   g_ssrc[MAXE];           // src ids sorted by dst
__device__ int   g_bsum[MAXBLK];
__device__ int   g_bbase[MAXBLK];

// ---------------- helpers ---------------------------------------------------
__device__ __forceinline__ unsigned f2tf32(float v) {
    unsigned r;
    asm("cvt.rna.tf32.f32 %0, %1;" : "=r"(r) : "f"(v));
    return r;
}

__device__ __forceinline__ void cp16(float* dst_smem, const float* src, bool pred) {
    unsigned d = (unsigned)__cvta_generic_to_shared(dst_smem);
    int sz = pred ? 16 : 0;
    asm volatile("cp.async.cg.shared.global [%0], [%1], 16, %2;\n"
                 :: "r"(d), "l"(src), "r"(sz));
}
__device__ __forceinline__ void cp_commit() {
    asm volatile("cp.async.commit_group;\n");
}
template <int NW>
__device__ __forceinline__ void cp_wait() {
    asm volatile("cp.async.wait_group %0;\n" :: "n"(NW));
}

__device__ __forceinline__ float gelu_exact(float v) {
    return 0.5f * v * (1.0f + erff(v * 0.7071067811865476f));
}

// ---------------- init ------------------------------------------------------
__global__ void k_init(int N) {
    int i = blockIdx.x * blockDim.x + threadIdx.x;
    if (i < N) {
        g_deg[i] = 0.f; g_mean[i] = 0.f; g_var[i] = 0.f;
        g_indeg[i] = 0; g_cursor[i] = 0;
    }
}

// ---------------- edge pass 0: histograms -----------------------------------
__global__ void k_edge0(const int* __restrict__ ei, int E) {
    int e = blockIdx.x * blockDim.x + threadIdx.x;
    if (e >= E) return;
    int s = ei[e], d = ei[E + e];
    atomicAdd(&g_deg[s], 1.0f);
    atomicAdd(&g_indeg[d], 1);
}

// ---------------- scan (3 kernels) ------------------------------------------
__global__ void k_scan1(int N) {
    __shared__ int sm[256];
    int base = blockIdx.x * SCANB + threadIdx.x * 4;
    int t = 0;
#pragma unroll
    for (int j = 0; j < 4; j++)
        if (base + j < N) t += g_indeg[base + j];
    sm[threadIdx.x] = t;
    __syncthreads();
    for (int o = 128; o > 0; o >>= 1) {
        if (threadIdx.x < o) sm[threadIdx.x] += sm[threadIdx.x + o];
        __syncthreads();
    }
    if (threadIdx.x == 0) g_bsum[blockIdx.x] = sm[0];
}

__global__ void k_scan2(int nb) {
    if (threadIdx.x == 0 && blockIdx.x == 0) {
        int run = 0;
        for (int b = 0; b < nb; b++) { g_bbase[b] = run; run += g_bsum[b]; }
    }
}

__global__ void k_scan3(int N) {
    __shared__ int sm[256];
    int tid = threadIdx.x;
    int base = blockIdx.x * SCANB + tid * 4;
    int v[4] = {0, 0, 0, 0};
#pragma unroll
    for (int j = 0; j < 4; j++)
        if (base + j < N) v[j] = g_indeg[base + j];
    int tsum = v[0] + v[1] + v[2] + v[3];
    sm[tid] = tsum;
    __syncthreads();
    // Hillis-Steele inclusive scan
    for (int o = 1; o < 256; o <<= 1) {
        int t = (tid >= o) ? sm[tid - o] : 0;
        __syncthreads();
        sm[tid] += t;
        __syncthreads();
    }
    int excl = sm[tid] - tsum;
    int g = g_bbase[blockIdx.x] + excl;
#pragma unroll
    for (int j = 0; j < 4; j++) {
        if (base + j < N) g_off[base + j] = g;
        g += v[j];
    }
}

// ---------------- scatter: sort src ids by dst ------------------------------
__global__ void k_scatter(const int* __restrict__ ei, int E) {
    int e = blockIdx.x * blockDim.x + threadIdx.x;
    if (e >= E) return;
    int s = ei[e], d = ei[E + e];
    int pos = g_off[d] + atomicAdd(&g_cursor[d], 1);
    g_ssrc[pos] = s;
}

// ---------------- tf32 tensor-core GEMM, cp.async double-buffered -----------
// Tile 128x128, BK=32, 256 threads = 8 warps (4m x 2n), warp tile 32x64.
// ACT: 0 = none, 1 = bias + exact GELU, 2 = bias + residual add
#define SA 36
#define SB 136
#define GEMM_SMEM (2 * (128 * SA + 32 * SB) * 4)

template <int ACT>
__global__ __launch_bounds__(256) void k_gemm_tc(
        int M, int N, int K,
        const float* __restrict__ A, const float* __restrict__ B,
        const float* __restrict__ bias, const float* __restrict__ res,
        float* __restrict__ Cout) {
    extern __shared__ float smem[];
    float* sA = smem;                       // 2 x 128 x SA
    float* sB = smem + 2 * 128 * SA;        // 2 x 32 x SB

    int tid = threadIdx.x;
    int row0 = blockIdx.y * 128, col0 = blockIdx.x * 128;
    int wid = tid >> 5, lane = tid & 31;
    int wm = wid & 3, wn = wid >> 2;
    int t4r = lane >> 2, t4c = lane & 3;

    float acc[2][8][4];
#pragma unroll
    for (int mt = 0; mt < 2; mt++)
#pragma unroll
        for (int nt = 0; nt < 8; nt++)
#pragma unroll
            for (int i = 0; i < 4; i++) acc[mt][nt][i] = 0.f;

    int T = K >> 5;

    // tile loader: stage st, k-tile t
    auto load_tile = [&](int t, int st) {
        int k0 = t * 32;
        float* dA = sA + st * 128 * SA;
        float* dB = sB + st * 32 * SB;
#pragma unroll
        for (int j = 0; j < 4; j++) {
            int i = tid + j * 256;
            int r = i >> 3, c = (i & 7) * 4;
            cp16(&dA[r * SA + c], &A[(size_t)(row0 + r) * K + k0 + c], row0 + r < M);
        }
#pragma unroll
        for (int j = 0; j < 4; j++) {
            int i = tid + j * 256;
            int r = i >> 5, c = (i & 31) * 4;
            cp16(&dB[r * SB + c], &B[(size_t)(k0 + r) * N + col0 + c], true);
        }
        cp_commit();
    };

    load_tile(0, 0);
    if (T > 1) load_tile(1, 1);

    for (int t = 0; t < T; t++) {
        if (t == T - 1) cp_wait<0>(); else cp_wait<1>();
        __syncthreads();
        const float* At = sA + (t & 1) * 128 * SA;
        const float* Bt = sB + (t & 1) * 32 * SB;
#pragma unroll
        for (int kk = 0; kk < 32; kk += 8) {
            unsigned a[2][4];
#pragma unroll
            for (int mt = 0; mt < 2; mt++) {
                int r = wm * 32 + mt * 16 + t4r;
                a[mt][0] = f2tf32(At[r * SA + kk + t4c]);
                a[mt][1] = f2tf32(At[(r + 8) * SA + kk + t4c]);
                a[mt][2] = f2tf32(At[r * SA + kk + t4c + 4]);
                a[mt][3] = f2tf32(At[(r + 8) * SA + kk + t4c + 4]);
            }
#pragma unroll
            for (int nt = 0; nt < 8; nt++) {
                int n = wn * 64 + nt * 8 + t4r;
                unsigned b0 = f2tf32(Bt[(kk + t4c) * SB + n]);
                unsigned b1 = f2tf32(Bt[(kk + t4c + 4) * SB + n]);
#pragma unroll
                for (int mt = 0; mt < 2; mt++) {
                    asm volatile(
                        "mma.sync.aligned.m16n8k8.row.col.f32.tf32.tf32.f32 "
                        "{%0,%1,%2,%3}, {%4,%5,%6,%7}, {%8,%9}, {%0,%1,%2,%3};"
                        : "+f"(acc[mt][nt][0]), "+f"(acc[mt][nt][1]),
                          "+f"(acc[mt][nt][2]), "+f"(acc[mt][nt][3])
                        : "r"(a[mt][0]), "r"(a[mt][1]), "r"(a[mt][2]), "r"(a[mt][3]),
                          "r"(b0), "r"(b1));
                }
            }
        }
        __syncthreads();
        if (t + 2 < T) load_tile(t + 2, t & 1);
    }

    // epilogue
#pragma unroll
    for (int mt = 0; mt < 2; mt++) {
#pragma unroll
        for (int nt = 0; nt < 8; nt++) {
            int c = col0 + wn * 64 + nt * 8 + 2 * t4c;
            float bb0 = bias ? bias[c] : 0.f;
            float bb1 = bias ? bias[c + 1] : 0.f;
#pragma unroll
            for (int half = 0; half < 2; half++) {
                int r = row0 + wm * 32 + mt * 16 + t4r + half * 8;
                if (r >= M) continue;
                float v0 = acc[mt][nt][half * 2 + 0] + bb0;
                float v1 = acc[mt][nt][half * 2 + 1] + bb1;
                if (ACT == 1) { v0 = gelu_exact(v0); v1 = gelu_exact(v1); }
                if (ACT == 2) {
                    float2 rv = *(const float2*)&res[(size_t)r * N + c];
                    v0 += rv.x; v1 += rv.y;
                }
                float2 o = {v0, v1};
                *(float2*)&Cout[(size_t)r * N + c] = o;
            }
        }
    }
}

// ---------------- attention scalars -----------------------------------------
__global__ void k_attn(int N, const float* __restrict__ att_src,
                       const float* __restrict__ att_dst) {
    int i = blockIdx.x * blockDim.x + threadIdx.x;
    if (i >= N * NH) return;
    int n = i >> 3, h = i & 7;
    const float* hp = &g_h[n * DIM + h * HC];
    float s = 0.f, d = 0.f;
#pragma unroll
    for (int c = 0; c < HC; c++) {
        float v = hp[c];
        s += v * __ldg(&att_src[h * HC + c]);
        d += v * __ldg(&att_dst[h * HC + c]);
    }
    g_as[i] = s;
    g_ad[i] = d;
}

// ---------------- sorted aggregation: warp per dst node ---------------------
// Computes softmax-weighted aggregation + self loop + bias + rowmean + di.
__global__ void k_aggsort(int N, const float* __restrict__ gat_bias) {
    int gid = blockIdx.x * blockDim.x + threadIdx.x;
    int n = gid >> 5;
    if (n >= N) return;
    int lane = gid & 31;
    int h = lane >> 2;
    int off = g_off[n], cnt = g_indeg[n];
    float ad = g_ad[n * 8 + h];

    float4 acc = make_float4(0.f, 0.f, 0.f, 0.f);
    float den = 0.f;

    int i = 0;
    for (; i + 2 <= cnt; i += 2) {
        int s0 = __ldg(&g_ssrc[off + i]);
        int s1 = __ldg(&g_ssrc[off + i + 1]);
        float as0 = __ldg(&g_as[s0 * 8 + h]);
        float as1 = __ldg(&g_as[s1 * 8 + h]);
        float4 h0 = __ldg((const float4*)&g_h[(size_t)s0 * DIM + lane * 4]);
        float4 h1 = __ldg((const float4*)&g_h[(size_t)s1 * DIM + lane * 4]);
        float v0 = as0 + ad; v0 = v0 > 0.f ? v0 : 0.2f * v0;
        float v1 = as1 + ad; v1 = v1 > 0.f ? v1 : 0.2f * v1;
        float w0 = (s0 == n) ? 0.f : __expf(v0);
        float w1 = (s1 == n) ? 0.f : __expf(v1);
        den += w0 + w1;
        acc.x += w0 * h0.x + w1 * h1.x;
        acc.y += w0 * h0.y + w1 * h1.y;
        acc.z += w0 * h0.z + w1 * h1.z;
        acc.w += w0 * h0.w + w1 * h1.w;
    }
    if (i < cnt) {
        int s0 = __ldg(&g_ssrc[off + i]);
        float as0 = __ldg(&g_as[s0 * 8 + h]);
        float4 h0 = __ldg((const float4*)&g_h[(size_t)s0 * DIM + lane * 4]);
        float v0 = as0 + ad; v0 = v0 > 0.f ? v0 : 0.2f * v0;
        float w0 = (s0 == n) ? 0.f : __expf(v0);
        den += w0;
        acc.x += w0 * h0.x; acc.y += w0 * h0.y;
        acc.z += w0 * h0.z; acc.w += w0 * h0.w;
    }

    // self loop
    float asn = g_as[n * 8 + h];
    float vs = asn + ad; vs = vs > 0.f ? vs : 0.2f * vs;
    float ws = __expf(vs);
    float4 hn = ((const float4*)g_h)[(size_t)n * 32 + lane];
    den += ws;
    acc.x += ws * hn.x; acc.y += ws * hn.y;
    acc.z += ws * hn.z; acc.w += ws * hn.w;

    float inv = 1.f / (den + 1e-16f);
    float4 b = ((const float4*)gat_bias)[lane];
    float4 y;
    y.x = acc.x * inv + b.x;
    y.y = acc.y * inv + b.y;
    y.z = acc.z * inv + b.z;
    y.w = acc.w * inv + b.w;
    ((float4*)g_agg)[(size_t)n * 32 + lane] = y;

    float sum = y.x + y.y + y.z + y.w;
#pragma unroll
    for (int o = 16; o > 0; o >>= 1) sum += __shfl_xor_sync(0xffffffffu, sum, o);
    if (lane == 0) {
        g_r[n] = sum * (1.f / 128.f);
        g_di[n] = rsqrtf(g_deg[n] + 1e-6f);
    }
}

// ---------------- laplacian mean (scalar per edge) --------------------------
__global__ void k_edge_mean(const int* __restrict__ ei, int E) {
    int e = blockIdx.x * blockDim.x + threadIdx.x;
    if (e >= E) return;
    int s = ei[e], d = ei[E + e];
    atomicAdd(&g_mean[s], g_di[s] * g_di[d] * g_r[d]);
}

// ---------------- per-node q ------------------------------------------------
__global__ void k_q(int N) {
    int gid = blockIdx.x * blockDim.x + threadIdx.x;
    int n = gid >> 5;
    if (n >= N) return;
    int lane = gid & 31;
    float m = g_mean[n];
    float4 y = ((const float4*)g_agg)[n * 32 + lane];
    float a0 = y.x - m, a1 = y.y - m, a2 = y.z - m, a3 = y.w - m;
    float s = a0 * a0 + a1 * a1 + a2 * a2 + a3 * a3;
#pragma unroll
    for (int o = 16; o > 0; o >>= 1) s += __shfl_xor_sync(0xffffffffu, s, o);
    if (lane == 0) g_q[n] = s * (1.f / 128.f);
}

// ---------------- laplacian var (scalar per edge) ---------------------------
__global__ void k_edge_var(const int* __restrict__ ei, int E) {
    int e = blockIdx.x * blockDim.x + threadIdx.x;
    if (e >= E) return;
    int s = ei[e], d = ei[E + e];
    atomicAdd(&g_var[s], g_di[s] * g_di[d] * g_q[d]);
}

// ---------------- laplacian norm + residual + LayerNorm ---------------------
__global__ void k_lnfuse(int N, const float* __restrict__ x,
                         const float* __restrict__ s1, const float* __restrict__ b1,
                         const float* __restrict__ s2, const float* __restrict__ b2) {
    int gid = blockIdx.x * blockDim.x + threadIdx.x;
    int n = gid >> 5;
    if (n >= N) return;
    int lane = gid & 31;
    float m = g_mean[n];
    float inv1 = 1.f / sqrtf(g_var[n] + 1e-6f);
    float4 y = ((const float4*)g_agg)[n * 32 + lane];
    float4 xv = ((const float4*)x)[(size_t)n * 32 + lane];
    float4 sc1 = ((const float4*)s1)[lane];
    float4 bb1 = ((const float4*)b1)[lane];
    float4 sc2 = ((const float4*)s2)[lane];
    float4 bb2 = ((const float4*)b2)[lane];
    float o0 = (y.x - m) * inv1 * sc1.x + bb1.x + xv.x;
    float o1 = (y.y - m) * inv1 * sc1.y + bb1.y + xv.y;
    float o2 = (y.z - m) * inv1 * sc1.z + bb1.z + xv.z;
    float o3 = (y.w - m) * inv1 * sc1.w + bb1.w + xv.w;
    float sum = o0 + o1 + o2 + o3;
#pragma unroll
    for (int o = 16; o > 0; o >>= 1) sum += __shfl_xor_sync(0xffffffffu, sum, o);
    float mu = sum * (1.f / 128.f);
    float c0 = o0 - mu, c1 = o1 - mu, c2 = o2 - mu, c3 = o3 - mu;
    float vs = c0 * c0 + c1 * c1 + c2 * c2 + c3 * c3;
#pragma unroll
    for (int o = 16; o > 0; o >>= 1) vs += __shfl_xor_sync(0xffffffffu, vs, o);
    float inv2 = rsqrtf(vs * (1.f / 128.f) + 1e-5f);
    float4 r;
    r.x = c0 * inv2 * sc2.x + bb2.x;
    r.y = c1 * inv2 * sc2.y + bb2.y;
    r.z = c2 * inv2 * sc2.z + bb2.z;
    r.w = c3 * inv2 * sc2.w + bb2.w;
    ((float4*)g_ln)[n * 32 + lane] = r;
}

// ---------------- final L2 normalize ----------------------------------------
__global__ void k_l2norm(int N, float* __restrict__ out) {
    int gid = blockIdx.x * blockDim.x + threadIdx.x;
    int n = gid >> 5;
    if (n >= N) return;
    int lane = gid & 31;
    float4 z = ((const float4*)g_z)[n * 32 + lane];
    float s = z.x * z.x + z.y * z.y + z.z * z.z + z.w * z.w;
#pragma unroll
    for (int o = 16; o > 0; o >>= 1) s += __shfl_xor_sync(0xffffffffu, s, o);
    float inv = 1.f / fmaxf(sqrtf(s), 1e-12f);
    float4 r;
    r.x = z.x * inv; r.y = z.y * inv; r.z = z.z * inv; r.w = z.w * inv;
    ((float4*)out)[(size_t)n * 32 + lane] = r;
}

// ---------------- launch ----------------------------------------------------
extern "C" void kernel_launch(void* const* d_in, const int* in_sizes, int n_in,
                              void* d_out, int out_size) {
    const float* x        = (const float*)d_in[0];
    const int* ei         = (const int*)d_in[1];
    const float* W        = (const float*)d_in[2];
    const float* att_src  = (const float*)d_in[3];
    const float* att_dst  = (const float*)d_in[4];
    const float* gat_bias = (const float*)d_in[5];
    const float* ln1s     = (const float*)d_in[6];
    const float* ln1b     = (const float*)d_in[7];
    const float* ln2s     = (const float*)d_in[8];
    const float* ln2b     = (const float*)d_in[9];
    const float* W1       = (const float*)d_in[10];
    const float* b1       = (const float*)d_in[11];
    const float* W2       = (const float*)d_in[12];
    const float* b2       = (const float*)d_in[13];
    float* out            = (float*)d_out;

    int N = in_sizes[0] / DIM;
    int E = in_sizes[1] / 2;
    int nb = (N + SCANB - 1) / SCANB;
    int mb = (N + 127) / 128;

    float *p_h, *p_ln, *p_t, *p_z;
    cudaGetSymbolAddress((void**)&p_h, g_h);
    cudaGetSymbolAddress((void**)&p_ln, g_ln);
    cudaGetSymbolAddress((void**)&p_t, g_t);
    cudaGetSymbolAddress((void**)&p_z, g_z);

    cudaFuncSetAttribute(k_gemm_tc<0>, cudaFuncAttributeMaxDynamicSharedMemorySize, GEMM_SMEM);
    cudaFuncSetAttribute(k_gemm_tc<1>, cudaFuncAttributeMaxDynamicSharedMemorySize, GEMM_SMEM);
    cudaFuncSetAttribute(k_gemm_tc<2>, cudaFuncAttributeMaxDynamicSharedMemorySize, GEMM_SMEM);

    // init + build dst-sorted edge structure
    k_init<<<(N + 255) / 256, 256>>>(N);
    k_edge0<<<(E + 255) / 256, 256>>>(ei, E);
    k_scan1<<<nb, 256>>>(N);
    k_scan2<<<1, 1>>>(nb);
    k_scan3<<<nb, 256>>>(N);
    k_scatter<<<(E + 255) / 256, 256>>>(ei, E);

    // h = x @ W
    k_gemm_tc<0><<<dim3(1, mb), 256, GEMM_SMEM>>>(N, DIM, DIM, x, W, nullptr, nullptr, p_h);

    // attention scalars
    k_attn<<<(N * NH + 255) / 256, 256>>>(N, att_src, att_dst);

    // sorted aggregation + GAT finalize
    k_aggsort<<<(N * 32 + 255) / 256, 256>>>(N, gat_bias);

    // laplacian norm (scalar edge passes)
    k_edge_mean<<<(E + 255) / 256, 256>>>(ei, E);
    k_q<<<(N * 32 + 255) / 256, 256>>>(N);
    k_edge_var<<<(E + 255) / 256, 256>>>(ei, E);

    // laplacian norm + residual + LayerNorm
    k_lnfuse<<<(N * 32 + 255) / 256, 256>>>(N, x, ln1s, ln1b, ln2s, ln2b);

    // MLP
    k_gemm_tc<1><<<dim3(2, mb), 256, GEMM_SMEM>>>(N, 2 * DIM, DIM, p_ln, W1, b1, nullptr, p_t);
    k_gemm_tc<2><<<dim3(1, mb), 256, GEMM_SMEM>>>(N, DIM, 2 * DIM, p_t, W2, b2, p_ln, p_z);

    // final row-wise L2 normalize
    k_l2norm<<<(N * 32 + 255) / 256, 256>>>(N, out);
}

// round 5
// speedup vs baseline: 3.5013x; 1.0859x over previous
#include <cuda_runtime.h>
#include <math.h>

#define MAXN 50000
#define MAXE 800000
#define DIM 128
#define NH 8
#define SCANB 1024
#define MAXBLK 64

// ---------------- scratch (static device globals; no allocation) ------------
__device__ float g_h[MAXN * DIM];        // h = x @ W
__device__ float g_as[MAXN * NH];        // per-node att_src dot
__device__ float g_ad[MAXN * NH];        // per-node att_dst dot
__device__ float g_agg[MAXN * DIM];      // GAT output y
__device__ float g_di[MAXN];             // rsqrt(outdeg + eps)
__device__ float g_p[MAXN];              // di * rowmean(y)
__device__ float g_pq[MAXN];             // di * q
__device__ float g_mean[MAXN];           // laplacian mean
__device__ float g_ln[MAXN * DIM];       // after LayerNorm (MLP input + residual)
__device__ float g_t[MAXN * 2 * DIM];    // GELU intermediate
__device__ int   g_indeg[MAXN];
__device__ int   g_outdeg[MAXN];
__device__ int   g_cin[MAXN];
__device__ int   g_cout[MAXN];
__device__ int   g_offi[MAXN];           // CSR offsets by dst
__device__ int   g_offo[MAXN];           // CSR offsets by src
__device__ int   g_ssrc[MAXE];           // src ids sorted by dst
__device__ int   g_sdst[MAXE];           // dst ids sorted by src
__device__ int   g_bsum_i[MAXBLK];
__device__ int   g_bsum_o[MAXBLK];

// ---------------- helpers ---------------------------------------------------
__device__ __forceinline__ unsigned f2tf32(float v) {
    unsigned r;
    asm("cvt.rna.tf32.f32 %0, %1;" : "=r"(r) : "f"(v));
    return r;
}

__device__ __forceinline__ void cp16(float* dst_smem, const float* src, bool pred) {
    unsigned d = (unsigned)__cvta_generic_to_shared(dst_smem);
    int sz = pred ? 16 : 0;
    asm volatile("cp.async.cg.shared.global [%0], [%1], 16, %2;\n"
                 :: "r"(d), "l"(src), "r"(sz));
}
__device__ __forceinline__ void cp_commit() {
    asm volatile("cp.async.commit_group;\n");
}
template <int NW>
__device__ __forceinline__ void cp_wait() {
    asm volatile("cp.async.wait_group %0;\n" :: "n"(NW));
}

__device__ __forceinline__ float gelu_exact(float v) {
    return 0.5f * v * (1.0f + erff(v * 0.7071067811865476f));
}

__device__ __forceinline__ float warp_sum(float s) {
#pragma unroll
    for (int o = 16; o > 0; o >>= 1) s += __shfl_xor_sync(0xffffffffu, s, o);
    return s;
}

// ---------------- init ------------------------------------------------------
__global__ void k_init(int N) {
    int i = blockIdx.x * blockDim.x + threadIdx.x;
    if (i < N) { g_indeg[i] = 0; g_outdeg[i] = 0; g_cin[i] = 0; g_cout[i] = 0; }
}

// ---------------- edge histograms -------------------------------------------
__global__ void k_edge0(const int* __restrict__ ei, int E) {
    int e = blockIdx.x * blockDim.x + threadIdx.x;
    if (e >= E) return;
    atomicAdd(&g_outdeg[ei[e]], 1);
    atomicAdd(&g_indeg[ei[E + e]], 1);
}

// ---------------- scan (2 kernels, both histograms) -------------------------
__global__ void k_scan1(int N) {
    __shared__ int smi[256], smo[256];
    int base = blockIdx.x * SCANB + threadIdx.x * 4;
    int ti = 0, to = 0;
#pragma unroll
    for (int j = 0; j < 4; j++)
        if (base + j < N) { ti += g_indeg[base + j]; to += g_outdeg[base + j]; }
    smi[threadIdx.x] = ti; smo[threadIdx.x] = to;
    __syncthreads();
    for (int o = 128; o > 0; o >>= 1) {
        if (threadIdx.x < o) { smi[threadIdx.x] += smi[threadIdx.x + o];
                               smo[threadIdx.x] += smo[threadIdx.x + o]; }
        __syncthreads();
    }
    if (threadIdx.x == 0) { g_bsum_i[blockIdx.x] = smi[0]; g_bsum_o[blockIdx.x] = smo[0]; }
}

__global__ void k_scan3(int N) {
    __shared__ int smi[256], smo[256];
    __shared__ int basei, baseo;
    int tid = threadIdx.x;
    if (tid == 0) {
        int bi = 0, bo = 0;
        for (int b = 0; b < (int)blockIdx.x; b++) { bi += g_bsum_i[b]; bo += g_bsum_o[b]; }
        basei = bi; baseo = bo;
    }
    int base = blockIdx.x * SCANB + tid * 4;
    int vi[4] = {0,0,0,0}, vo[4] = {0,0,0,0};
#pragma unroll
    for (int j = 0; j < 4; j++)
        if (base + j < N) { vi[j] = g_indeg[base + j]; vo[j] = g_outdeg[base + j]; }
    int tsi = vi[0]+vi[1]+vi[2]+vi[3], tso = vo[0]+vo[1]+vo[2]+vo[3];
    smi[tid] = tsi; smo[tid] = tso;
    __syncthreads();
    for (int o = 1; o < 256; o <<= 1) {
        int a = (tid >= o) ? smi[tid - o] : 0;
        int b = (tid >= o) ? smo[tid - o] : 0;
        __syncthreads();
        smi[tid] += a; smo[tid] += b;
        __syncthreads();
    }
    int gi = basei + smi[tid] - tsi;
    int go = baseo + smo[tid] - tso;
#pragma unroll
    for (int j = 0; j < 4; j++) {
        if (base + j < N) { g_offi[base + j] = gi; g_offo[base + j] = go; }
        gi += vi[j]; go += vo[j];
    }
}

// ---------------- scatter: build both CSRs ----------------------------------
__global__ void k_scatter(const int* __restrict__ ei, int E) {
    int e = blockIdx.x * blockDim.x + threadIdx.x;
    if (e >= E) return;
    int s = ei[e], d = ei[E + e];
    g_ssrc[g_offi[d] + atomicAdd(&g_cin[d], 1)] = s;
    g_sdst[g_offo[s] + atomicAdd(&g_cout[s], 1)] = d;
}

// ---------------- tf32 TC GEMM, cp.async double-buffered --------------------
// Tile 128x128, BK=32, 256 threads = 8 warps (4m x 2n), warp tile 32x64.
// ACT: 1 = bias + GELU, 3 = plain + fused attention dots, 4 = bias + residual + L2norm
#define SA 36
#define SB 136
#define GEMM_SMEM (2 * (128 * SA + 32 * SB) * 4)
#define ZS 132

template <int ACT>
__global__ __launch_bounds__(256) void k_gemm_tc(
        int M, int N, int K,
        const float* __restrict__ A, const float* __restrict__ B,
        const float* __restrict__ bias, const float* __restrict__ res,
        float* __restrict__ Cout,
        const float* __restrict__ asrc, const float* __restrict__ adst) {
    extern __shared__ float smem[];
    float* sA = smem;
    float* sB = smem + 2 * 128 * SA;

    int tid = threadIdx.x;
    int row0 = blockIdx.y * 128, col0 = blockIdx.x * 128;
    int wid = tid >> 5, lane = tid & 31;
    int wm = wid & 3, wn = wid >> 2;
    int t4r = lane >> 2, t4c = lane & 3;

    float acc[2][8][4];
#pragma unroll
    for (int mt = 0; mt < 2; mt++)
#pragma unroll
        for (int nt = 0; nt < 8; nt++)
#pragma unroll
            for (int i = 0; i < 4; i++) acc[mt][nt][i] = 0.f;

    int T = K >> 5;

    auto load_tile = [&](int t, int st) {
        int k0 = t * 32;
        float* dA = sA + st * 128 * SA;
        float* dB = sB + st * 32 * SB;
#pragma unroll
        for (int j = 0; j < 4; j++) {
            int i = tid + j * 256;
            int r = i >> 3, c = (i & 7) * 4;
            cp16(&dA[r * SA + c], &A[(size_t)(row0 + r) * K + k0 + c], row0 + r < M);
        }
#pragma unroll
        for (int j = 0; j < 4; j++) {
            int i = tid + j * 256;
            int r = i >> 5, c = (i & 31) * 4;
            cp16(&dB[r * SB + c], &B[(size_t)(k0 + r) * N + col0 + c], true);
        }
        cp_commit();
    };

    load_tile(0, 0);
    if (T > 1) load_tile(1, 1);

    for (int t = 0; t < T; t++) {
        if (t == T - 1) cp_wait<0>(); else cp_wait<1>();
        __syncthreads();
        const float* At = sA + (t & 1) * 128 * SA;
        const float* Bt = sB + (t & 1) * 32 * SB;
#pragma unroll
        for (int kk = 0; kk < 32; kk += 8) {
            unsigned a[2][4];
#pragma unroll
            for (int mt = 0; mt < 2; mt++) {
                int r = wm * 32 + mt * 16 + t4r;
                a[mt][0] = f2tf32(At[r * SA + kk + t4c]);
                a[mt][1] = f2tf32(At[(r + 8) * SA + kk + t4c]);
                a[mt][2] = f2tf32(At[r * SA + kk + t4c + 4]);
                a[mt][3] = f2tf32(At[(r + 8) * SA + kk + t4c + 4]);
            }
#pragma unroll
            for (int nt = 0; nt < 8; nt++) {
                int n = wn * 64 + nt * 8 + t4r;
                unsigned b0 = f2tf32(Bt[(kk + t4c) * SB + n]);
                unsigned b1 = f2tf32(Bt[(kk + t4c + 4) * SB + n]);
#pragma unroll
                for (int mt = 0; mt < 2; mt++) {
                    asm volatile(
                        "mma.sync.aligned.m16n8k8.row.col.f32.tf32.tf32.f32 "
                        "{%0,%1,%2,%3}, {%4,%5,%6,%7}, {%8,%9}, {%0,%1,%2,%3};"
                        : "+f"(acc[mt][nt][0]), "+f"(acc[mt][nt][1]),
                          "+f"(acc[mt][nt][2]), "+f"(acc[mt][nt][3])
                        : "r"(a[mt][0]), "r"(a[mt][1]), "r"(a[mt][2]), "r"(a[mt][3]),
                          "r"(b0), "r"(b1));
                }
            }
        }
        __syncthreads();
        if (t + 2 < T) load_tile(t + 2, t & 1);
    }

    if (ACT == 1) {
#pragma unroll
        for (int mt = 0; mt < 2; mt++)
#pragma unroll
            for (int nt = 0; nt < 8; nt++) {
                int c = col0 + wn * 64 + nt * 8 + 2 * t4c;
                float bb0 = bias[c], bb1 = bias[c + 1];
#pragma unroll
                for (int half = 0; half < 2; half++) {
                    int r = row0 + wm * 32 + mt * 16 + t4r + half * 8;
                    if (r >= M) continue;
                    float2 o = {gelu_exact(acc[mt][nt][half * 2 + 0] + bb0),
                                gelu_exact(acc[mt][nt][half * 2 + 1] + bb1)};
                    *(float2*)&Cout[(size_t)r * N + c] = o;
                }
            }
    } else if (ACT == 3) {
        // store h + fused attention dots (col0 == 0, N == 128)
#pragma unroll
        for (int mt = 0; mt < 2; mt++)
#pragma unroll
            for (int half = 0; half < 2; half++) {
                int r = row0 + wm * 32 + mt * 16 + t4r + half * 8;
                bool ok = r < M;
                float pa[4] = {0,0,0,0}, pd[4] = {0,0,0,0};
#pragma unroll
                for (int nt = 0; nt < 8; nt++) {
                    int c = wn * 64 + nt * 8 + 2 * t4c;
                    float v0 = acc[mt][nt][half * 2 + 0];
                    float v1 = acc[mt][nt][half * 2 + 1];
                    if (ok) {
                        float2 o = {v0, v1};
                        *(float2*)&Cout[(size_t)r * DIM + c] = o;
                    }
                    int p = nt >> 1;
                    pa[p] += v0 * __ldg(&asrc[c]) + v1 * __ldg(&asrc[c + 1]);
                    pd[p] += v0 * __ldg(&adst[c]) + v1 * __ldg(&adst[c + 1]);
                }
#pragma unroll
                for (int p = 0; p < 4; p++) {
                    pa[p] += __shfl_xor_sync(0xffffffffu, pa[p], 1);
                    pa[p] += __shfl_xor_sync(0xffffffffu, pa[p], 2);
                    pd[p] += __shfl_xor_sync(0xffffffffu, pd[p], 1);
                    pd[p] += __shfl_xor_sync(0xffffffffu, pd[p], 2);
                }
                if (ok && t4c == 0) {
#pragma unroll
                    for (int p = 0; p < 4; p++) {
                        g_as[r * NH + wn * 4 + p] = pa[p];
                        g_ad[r * NH + wn * 4 + p] = pd[p];
                    }
                }
            }
    } else {  // ACT == 4: bias + residual + row L2 normalize (col0 == 0, N == 128)
        float* zs = smem;  // reuse pipeline smem: 128 x ZS
#pragma unroll
        for (int mt = 0; mt < 2; mt++)
#pragma unroll
            for (int nt = 0; nt < 8; nt++) {
                int c = wn * 64 + nt * 8 + 2 * t4c;
                float bb0 = bias[c], bb1 = bias[c + 1];
#pragma unroll
                for (int half = 0; half < 2; half++) {
                    int rl = wm * 32 + mt * 16 + t4r + half * 8;
                    int r = row0 + rl;
                    if (r >= M) continue;
                    float2 rv = *(const float2*)&res[(size_t)r * DIM + c];
                    zs[rl * ZS + c]     = acc[mt][nt][half * 2 + 0] + bb0 + rv.x;
                    zs[rl * ZS + c + 1] = acc[mt][nt][half * 2 + 1] + bb1 + rv.y;
                }
            }
        __syncthreads();
#pragma unroll
        for (int rr = 0; rr < 16; rr++) {
            int rl = wid * 16 + rr;
            int r = row0 + rl;
            if (r >= M) continue;
            float4 z = *(float4*)&zs[rl * ZS + lane * 4];
            float ss = warp_sum(z.x * z.x + z.y * z.y + z.z * z.z + z.w * z.w);
            float inv = 1.f / fmaxf(sqrtf(ss), 1e-12f);
            float4 o = {z.x * inv, z.y * inv, z.z * inv, z.w * inv};
            *(float4*)&Cout[(size_t)r * DIM + lane * 4] = o;
        }
    }
}

// ---------------- sorted aggregation: warp per dst node ---------------------
__global__ void k_aggsort(int N, const float* __restrict__ gat_bias) {
    int gid = blockIdx.x * blockDim.x + threadIdx.x;
    int n = gid >> 5;
    if (n >= N) return;
    int lane = gid & 31;
    int h = lane >> 2;
    int off = g_offi[n], cnt = g_indeg[n];
    float ad = g_ad[n * 8 + h];

    float4 acc = make_float4(0.f, 0.f, 0.f, 0.f);
    float den = 0.f;

    int i = 0;
    for (; i + 2 <= cnt; i += 2) {
        int s0 = __ldg(&g_ssrc[off + i]);
        int s1 = __ldg(&g_ssrc[off + i + 1]);
        float as0 = __ldg(&g_as[s0 * 8 + h]);
        float as1 = __ldg(&g_as[s1 * 8 + h]);
        float4 h0 = __ldg((const float4*)&g_h[(size_t)s0 * DIM + lane * 4]);
        float4 h1 = __ldg((const float4*)&g_h[(size_t)s1 * DIM + lane * 4]);
        float v0 = as0 + ad; v0 = v0 > 0.f ? v0 : 0.2f * v0;
        float v1 = as1 + ad; v1 = v1 > 0.f ? v1 : 0.2f * v1;
        float w0 = (s0 == n) ? 0.f : __expf(v0);
        float w1 = (s1 == n) ? 0.f : __expf(v1);
        den += w0 + w1;
        acc.x += w0 * h0.x + w1 * h1.x;
        acc.y += w0 * h0.y + w1 * h1.y;
        acc.z += w0 * h0.z + w1 * h1.z;
        acc.w += w0 * h0.w + w1 * h1.w;
    }
    if (i < cnt) {
        int s0 = __ldg(&g_ssrc[off + i]);
        float as0 = __ldg(&g_as[s0 * 8 + h]);
        float4 h0 = __ldg((const float4*)&g_h[(size_t)s0 * DIM + lane * 4]);
        float v0 = as0 + ad; v0 = v0 > 0.f ? v0 : 0.2f * v0;
        float w0 = (s0 == n) ? 0.f : __expf(v0);
        den += w0;
        acc.x += w0 * h0.x; acc.y += w0 * h0.y;
        acc.z += w0 * h0.z; acc.w += w0 * h0.w;
    }

    // self loop
    float asn = g_as[n * 8 + h];
    float vs = asn + ad; vs = vs > 0.f ? vs : 0.2f * vs;
    float ws = __expf(vs);
    float4 hn = ((const float4*)g_h)[(size_t)n * 32 + lane];
    den += ws;
    acc.x += ws * hn.x; acc.y += ws * hn.y;
    acc.z += ws * hn.z; acc.w += ws * hn.w;

    float inv = 1.f / (den + 1e-16f);
    float4 b = ((const float4*)gat_bias)[lane];
    float4 y;
    y.x = acc.x * inv + b.x;
    y.y = acc.y * inv + b.y;
    y.z = acc.z * inv + b.z;
    y.w = acc.w * inv + b.w;
    ((float4*)g_agg)[(size_t)n * 32 + lane] = y;

    float sum = warp_sum(y.x + y.y + y.z + y.w);
    if (lane == 0) {
        float di = rsqrtf((float)g_outdeg[n] + 1e-6f);
        g_di[n] = di;
        g_p[n] = di * sum * (1.f / 128.f);
    }
}

// ---------------- laplacian pass 1: mean gather + q -------------------------
__global__ void k_lap1(int N) {
    int gid = blockIdx.x * blockDim.x + threadIdx.x;
    int n = gid >> 5;
    if (n >= N) return;
    int lane = gid & 31;
    int off = g_offo[n], cnt = g_outdeg[n];
    float s = 0.f;
    for (int i = lane; i < cnt; i += 32)
        s += __ldg(&g_p[__ldg(&g_sdst[off + i])]);
    s = warp_sum(s);
    float di = g_di[n];
    float mean = di * s;
    float4 y = ((const float4*)g_agg)[(size_t)n * 32 + lane];
    float a0 = y.x - mean, a1 = y.y - mean, a2 = y.z - mean, a3 = y.w - mean;
    float ss = warp_sum(a0 * a0 + a1 * a1 + a2 * a2 + a3 * a3);
    if (lane == 0) {
        g_mean[n] = mean;
        g_pq[n] = di * ss * (1.f / 128.f);
    }
}

// ---------------- laplacian pass 2: var gather + LapNorm + res + LayerNorm --
__global__ void k_lap2(int N, const float* __restrict__ x,
                       const float* __restrict__ s1, const float* __restrict__ b1,
                       const float* __restrict__ s2, const float* __restrict__ b2) {
    int gid = blockIdx.x * blockDim.x + threadIdx.x;
    int n = gid >> 5;
    if (n >= N) return;
    int lane = gid & 31;
    int off = g_offo[n], cnt = g_outdeg[n];
    float s = 0.f;
    for (int i = lane; i < cnt; i += 32)
        s += __ldg(&g_pq[__ldg(&g_sdst[off + i])]);
    s = warp_sum(s);
    float var = g_di[n] * s;
    float m = g_mean[n];
    float inv1 = 1.f / sqrtf(var + 1e-6f);

    float4 y = ((const float4*)g_agg)[(size_t)n * 32 + lane];
    float4 xv = ((const float4*)x)[(size_t)n * 32 + lane];
    float4 sc1 = ((const float4*)s1)[lane];
    float4 bb1 = ((const float4*)b1)[lane];
    float4 sc2 = ((const float4*)s2)[lane];
    float4 bb2 = ((const float4*)b2)[lane];
    float o0 = (y.x - m) * inv1 * sc1.x + bb1.x + xv.x;
    float o1 = (y.y - m) * inv1 * sc1.y + bb1.y + xv.y;
    float o2 = (y.z - m) * inv1 * sc1.z + bb1.z + xv.z;
    float o3 = (y.w - m) * inv1 * sc1.w + bb1.w + xv.w;
    float mu = warp_sum(o0 + o1 + o2 + o3) * (1.f / 128.f);
    float c0 = o0 - mu, c1 = o1 - mu, c2 = o2 - mu, c3 = o3 - mu;
    float vs = warp_sum(c0 * c0 + c1 * c1 + c2 * c2 + c3 * c3);
    float inv2 = rsqrtf(vs * (1.f / 128.f) + 1e-5f);
    float4 r;
    r.x = c0 * inv2 * sc2.x + bb2.x;
    r.y = c1 * inv2 * sc2.y + bb2.y;
    r.z = c2 * inv2 * sc2.z + bb2.z;
    r.w = c3 * inv2 * sc2.w + bb2.w;
    ((float4*)g_ln)[(size_t)n * 32 + lane] = r;
}

// ---------------- launch ----------------------------------------------------
extern "C" void kernel_launch(void* const* d_in, const int* in_sizes, int n_in,
                              void* d_out, int out_size) {
    const float* x        = (const float*)d_in[0];
    const int* ei         = (const int*)d_in[1];
    const float* W        = (const float*)d_in[2];
    const float* att_src  = (const float*)d_in[3];
    const float* att_dst  = (const float*)d_in[4];
    const float* gat_bias = (const float*)d_in[5];
    const float* ln1s     = (const float*)d_in[6];
    const float* ln1b     = (const float*)d_in[7];
    const float* ln2s     = (const float*)d_in[8];
    const float* ln2b     = (const float*)d_in[9];
    const float* W1       = (const float*)d_in[10];
    const float* b1       = (const float*)d_in[11];
    const float* W2       = (const float*)d_in[12];
    const float* b2       = (const float*)d_in[13];
    float* out            = (float*)d_out;

    int N = in_sizes[0] / DIM;
    int E = in_sizes[1] / 2;
    int nb = (N + SCANB - 1) / SCANB;
    int mb = (N + 127) / 128;

    float *p_h, *p_ln, *p_t;
    cudaGetSymbolAddress((void**)&p_h, g_h);
    cudaGetSymbolAddress((void**)&p_ln, g_ln);
    cudaGetSymbolAddress((void**)&p_t, g_t);

    cudaFuncSetAttribute(k_gemm_tc<1>, cudaFuncAttributeMaxDynamicSharedMemorySize, GEMM_SMEM);
    cudaFuncSetAttribute(k_gemm_tc<3>, cudaFuncAttributeMaxDynamicSharedMemorySize, GEMM_SMEM);
    cudaFuncSetAttribute(k_gemm_tc<4>, cudaFuncAttributeMaxDynamicSharedMemorySize, GEMM_SMEM);

    // build dual CSR
    k_init<<<(N + 255) / 256, 256>>>(N);
    k_edge0<<<(E + 255) / 256, 256>>>(ei, E);
    k_scan1<<<nb, 256>>>(N);
    k_scan3<<<nb, 256>>>(N);
    k_scatter<<<(E + 255) / 256, 256>>>(ei, E);

    // h = x @ W  (+ fused attention dots)
    k_gemm_tc<3><<<dim3(1, mb), 256, GEMM_SMEM>>>(N, DIM, DIM, x, W, nullptr, nullptr,
                                                  p_h, att_src, att_dst);

    // sorted aggregation + GAT finalize + p
    k_aggsort<<<(N * 32 + 255) / 256, 256>>>(N, gat_bias);

    // laplacian passes (gather-based) + fused LN
    k_lap1<<<(N * 32 + 255) / 256, 256>>>(N);
    k_lap2<<<(N * 32 + 255) / 256, 256>>>(N, x, ln1s, ln1b, ln2s, ln2b);

    // MLP (+ fused final L2 normalize)
    k_gemm_tc<1><<<dim3(2, mb), 256, GEMM_SMEM>>>(N, 2 * DIM, DIM, p_ln, W1, b1, nullptr,
                                                  p_t, nullptr, nullptr);
    k_gemm_tc<4><<<dim3(1, mb), 256, GEMM_SMEM>>>(N, DIM, 2 * DIM, p_t, W2, b2, p_ln,
                                                  out, nullptr, nullptr);
}

// round 6
// speedup vs baseline: 3.5579x; 1.0162x over previous
#include <cuda_runtime.h>
#include <cuda_fp16.h>
#include <math.h>

#define MAXN 50000
#define MAXE 800000
#define DIM 128
#define NH 8
#define SCANB 1024
#define MAXBLK 64

// ---------------- scratch (static device globals; no allocation) ------------
__device__ __half g_hh[MAXN * DIM];      // h = x @ W (fp16, only consumer: aggsort)
__device__ float g_as[MAXN * NH];        // per-node att_src dot
__device__ float g_ad[MAXN * NH];        // per-node att_dst dot
__device__ float g_agg[MAXN * DIM];      // GAT output y
__device__ float g_di[MAXN];             // rsqrt(outdeg + eps)
__device__ float g_p[MAXN];              // di * rowmean(y)
__device__ float g_pq[MAXN];             // di * q
__device__ float g_mean[MAXN];           // laplacian mean
__device__ float g_ln[MAXN * DIM];       // after LayerNorm (MLP input + residual)
__device__ float g_t[MAXN * 2 * DIM];    // GELU intermediate
__device__ int   g_indeg[MAXN];
__device__ int   g_outdeg[MAXN];
__device__ int   g_cin[MAXN];
__device__ int   g_cout[MAXN];
__device__ int   g_offi[MAXN];           // CSR offsets by dst
__device__ int   g_offo[MAXN];           // CSR offsets by src
__device__ int   g_ssrc[MAXE];           // src ids sorted by dst
__device__ int   g_sdst[MAXE];           // dst ids sorted by src
__device__ int   g_bsum_i[MAXBLK];
__device__ int   g_bsum_o[MAXBLK];

// ---------------- helpers ---------------------------------------------------
__device__ __forceinline__ unsigned f2tf32(float v) {
    unsigned r;
    asm("cvt.rna.tf32.f32 %0, %1;" : "=r"(r) : "f"(v));
    return r;
}

__device__ __forceinline__ void cp16(float* dst_smem, const float* src, bool pred) {
    unsigned d = (unsigned)__cvta_generic_to_shared(dst_smem);
    int sz = pred ? 16 : 0;
    asm volatile("cp.async.cg.shared.global [%0], [%1], 16, %2;\n"
                 :: "r"(d), "l"(src), "r"(sz));
}
__device__ __forceinline__ void cp_commit() {
    asm volatile("cp.async.commit_group;\n");
}
template <int NW>
__device__ __forceinline__ void cp_wait() {
    asm volatile("cp.async.wait_group %0;\n" :: "n"(NW));
}

__device__ __forceinline__ float gelu_exact(float v) {
    return 0.5f * v * (1.0f + erff(v * 0.7071067811865476f));
}

__device__ __forceinline__ float warp_sum(float s) {
#pragma unroll
    for (int o = 16; o > 0; o >>= 1) s += __shfl_xor_sync(0xffffffffu, s, o);
    return s;
}

// ---------------- init ------------------------------------------------------
__global__ void k_init(int N) {
    int i = blockIdx.x * blockDim.x + threadIdx.x;
    if (i < N) { g_indeg[i] = 0; g_outdeg[i] = 0; g_cin[i] = 0; g_cout[i] = 0; }
}

// ---------------- edge histograms -------------------------------------------
__global__ void k_edge0(const int* __restrict__ ei, int E) {
    int e = blockIdx.x * blockDim.x + threadIdx.x;
    if (e >= E) return;
    atomicAdd(&g_outdeg[ei[e]], 1);
    atomicAdd(&g_indeg[ei[E + e]], 1);
}

// ---------------- scan (2 kernels, both histograms) -------------------------
__global__ void k_scan1(int N) {
    __shared__ int smi[256], smo[256];
    int base = blockIdx.x * SCANB + threadIdx.x * 4;
    int ti = 0, to = 0;
#pragma unroll
    for (int j = 0; j < 4; j++)
        if (base + j < N) { ti += g_indeg[base + j]; to += g_outdeg[base + j]; }
    smi[threadIdx.x] = ti; smo[threadIdx.x] = to;
    __syncthreads();
    for (int o = 128; o > 0; o >>= 1) {
        if (threadIdx.x < o) { smi[threadIdx.x] += smi[threadIdx.x + o];
                               smo[threadIdx.x] += smo[threadIdx.x + o]; }
        __syncthreads();
    }
    if (threadIdx.x == 0) { g_bsum_i[blockIdx.x] = smi[0]; g_bsum_o[blockIdx.x] = smo[0]; }
}

__global__ void k_scan3(int N, int nb) {
    __shared__ int smi[256], smo[256];
    __shared__ int sbi[MAXBLK], sbo[MAXBLK];
    __shared__ int basei, baseo;
    int tid = threadIdx.x;
    if (tid < nb) { sbi[tid] = g_bsum_i[tid]; sbo[tid] = g_bsum_o[tid]; }
    __syncthreads();
    if (tid == 0) {
        int bi = 0, bo = 0;
        for (int b = 0; b < (int)blockIdx.x; b++) { bi += sbi[b]; bo += sbo[b]; }
        basei = bi; baseo = bo;
    }
    int base = blockIdx.x * SCANB + tid * 4;
    int vi[4] = {0,0,0,0}, vo[4] = {0,0,0,0};
#pragma unroll
    for (int j = 0; j < 4; j++)
        if (base + j < N) { vi[j] = g_indeg[base + j]; vo[j] = g_outdeg[base + j]; }
    int tsi = vi[0]+vi[1]+vi[2]+vi[3], tso = vo[0]+vo[1]+vo[2]+vo[3];
    smi[tid] = tsi; smo[tid] = tso;
    __syncthreads();
    for (int o = 1; o < 256; o <<= 1) {
        int a = (tid >= o) ? smi[tid - o] : 0;
        int b = (tid >= o) ? smo[tid - o] : 0;
        __syncthreads();
        smi[tid] += a; smo[tid] += b;
        __syncthreads();
    }
    int gi = basei + smi[tid] - tsi;
    int go = baseo + smo[tid] - tso;
#pragma unroll
    for (int j = 0; j < 4; j++) {
        if (base + j < N) { g_offi[base + j] = gi; g_offo[base + j] = go; }
        gi += vi[j]; go += vo[j];
    }
}

// ---------------- scatter: build both CSRs ----------------------------------
__global__ void k_scatter(const int* __restrict__ ei, int E) {
    int e = blockIdx.x * blockDim.x + threadIdx.x;
    if (e >= E) return;
    int s = ei[e], d = ei[E + e];
    g_ssrc[g_offi[d] + atomicAdd(&g_cin[d], 1)] = s;
    g_sdst[g_offo[s] + atomicAdd(&g_cout[s], 1)] = d;
}

// ---------------- tf32 TC GEMM, cp.async double-buffered --------------------
// Tile 128x128, BK=32, 256 threads = 8 warps (4m x 2n), warp tile 32x64.
// ACT: 1 = bias + GELU, 3 = fp16 store + fused attention dots, 4 = bias + residual + L2norm
#define SA 36
#define SB 136
#define GEMM_SMEM (2 * (128 * SA + 32 * SB) * 4)
#define ZS 132

template <int ACT>
__global__ __launch_bounds__(256) void k_gemm_tc(
        int M, int N, int K,
        const float* __restrict__ A, const float* __restrict__ B,
        const float* __restrict__ bias, const float* __restrict__ res,
        float* __restrict__ Cout,
        const float* __restrict__ asrc, const float* __restrict__ adst) {
    extern __shared__ float smem[];
    float* sA = smem;
    float* sB = smem + 2 * 128 * SA;

    int tid = threadIdx.x;
    int row0 = blockIdx.y * 128, col0 = blockIdx.x * 128;
    int wid = tid >> 5, lane = tid & 31;
    int wm = wid & 3, wn = wid >> 2;
    int t4r = lane >> 2, t4c = lane & 3;

    float acc[2][8][4];
#pragma unroll
    for (int mt = 0; mt < 2; mt++)
#pragma unroll
        for (int nt = 0; nt < 8; nt++)
#pragma unroll
            for (int i = 0; i < 4; i++) acc[mt][nt][i] = 0.f;

    int T = K >> 5;

    auto load_tile = [&](int t, int st) {
        int k0 = t * 32;
        float* dA = sA + st * 128 * SA;
        float* dB = sB + st * 32 * SB;
#pragma unroll
        for (int j = 0; j < 4; j++) {
            int i = tid + j * 256;
            int r = i >> 3, c = (i & 7) * 4;
            cp16(&dA[r * SA + c], &A[(size_t)(row0 + r) * K + k0 + c], row0 + r < M);
        }
#pragma unroll
        for (int j = 0; j < 4; j++) {
            int i = tid + j * 256;
            int r = i >> 5, c = (i & 31) * 4;
            cp16(&dB[r * SB + c], &B[(size_t)(k0 + r) * N + col0 + c], true);
        }
        cp_commit();
    };

    load_tile(0, 0);
    if (T > 1) load_tile(1, 1);

    for (int t = 0; t < T; t++) {
        if (t == T - 1) cp_wait<0>(); else cp_wait<1>();
        __syncthreads();
        const float* At = sA + (t & 1) * 128 * SA;
        const float* Bt = sB + (t & 1) * 32 * SB;
#pragma unroll
        for (int kk = 0; kk < 32; kk += 8) {
            unsigned a[2][4];
#pragma unroll
            for (int mt = 0; mt < 2; mt++) {
                int r = wm * 32 + mt * 16 + t4r;
                a[mt][0] = f2tf32(At[r * SA + kk + t4c]);
                a[mt][1] = f2tf32(At[(r + 8) * SA + kk + t4c]);
                a[mt][2] = f2tf32(At[r * SA + kk + t4c + 4]);
                a[mt][3] = f2tf32(At[(r + 8) * SA + kk + t4c + 4]);
            }
#pragma unroll
            for (int nt = 0; nt < 8; nt++) {
                int n = wn * 64 + nt * 8 + t4r;
                unsigned b0 = f2tf32(Bt[(kk + t4c) * SB + n]);
                unsigned b1 = f2tf32(Bt[(kk + t4c + 4) * SB + n]);
#pragma unroll
                for (int mt = 0; mt < 2; mt++) {
                    asm volatile(
                        "mma.sync.aligned.m16n8k8.row.col.f32.tf32.tf32.f32 "
                        "{%0,%1,%2,%3}, {%4,%5,%6,%7}, {%8,%9}, {%0,%1,%2,%3};"
                        : "+f"(acc[mt][nt][0]), "+f"(acc[mt][nt][1]),
                          "+f"(acc[mt][nt][2]), "+f"(acc[mt][nt][3])
                        : "r"(a[mt][0]), "r"(a[mt][1]), "r"(a[mt][2]), "r"(a[mt][3]),
                          "r"(b0), "r"(b1));
                }
            }
        }
        __syncthreads();
        if (t + 2 < T) load_tile(t + 2, t & 1);
    }

    if (ACT == 1) {
#pragma unroll
        for (int mt = 0; mt < 2; mt++)
#pragma unroll
            for (int nt = 0; nt < 8; nt++) {
                int c = col0 + wn * 64 + nt * 8 + 2 * t4c;
                float bb0 = bias[c], bb1 = bias[c + 1];
#pragma unroll
                for (int half = 0; half < 2; half++) {
                    int r = row0 + wm * 32 + mt * 16 + t4r + half * 8;
                    if (r >= M) continue;
                    float2 o = {gelu_exact(acc[mt][nt][half * 2 + 0] + bb0),
                                gelu_exact(acc[mt][nt][half * 2 + 1] + bb1)};
                    *(float2*)&Cout[(size_t)r * N + c] = o;
                }
            }
    } else if (ACT == 3) {
        // store h (fp16) + fused attention dots (col0 == 0, N == 128)
#pragma unroll
        for (int mt = 0; mt < 2; mt++)
#pragma unroll
            for (int half = 0; half < 2; half++) {
                int r = row0 + wm * 32 + mt * 16 + t4r + half * 8;
                bool ok = r < M;
                float pa[4] = {0,0,0,0}, pd[4] = {0,0,0,0};
#pragma unroll
                for (int nt = 0; nt < 8; nt++) {
                    int c = wn * 64 + nt * 8 + 2 * t4c;
                    float v0 = acc[mt][nt][half * 2 + 0];
                    float v1 = acc[mt][nt][half * 2 + 1];
                    if (ok) {
                        __half2 o = __floats2half2_rn(v0, v1);
                        *(__half2*)&g_hh[(size_t)r * DIM + c] = o;
                    }
                    int p = nt >> 1;
                    pa[p] += v0 * __ldg(&asrc[c]) + v1 * __ldg(&asrc[c + 1]);
                    pd[p] += v0 * __ldg(&adst[c]) + v1 * __ldg(&adst[c + 1]);
                }
#pragma unroll
                for (int p = 0; p < 4; p++) {
                    pa[p] += __shfl_xor_sync(0xffffffffu, pa[p], 1);
                    pa[p] += __shfl_xor_sync(0xffffffffu, pa[p], 2);
                    pd[p] += __shfl_xor_sync(0xffffffffu, pd[p], 1);
                    pd[p] += __shfl_xor_sync(0xffffffffu, pd[p], 2);
                }
                if (ok && t4c == 0) {
#pragma unroll
                    for (int p = 0; p < 4; p++) {
                        g_as[r * NH + wn * 4 + p] = pa[p];
                        g_ad[r * NH + wn * 4 + p] = pd[p];
                    }
                }
            }
    } else {  // ACT == 4: bias + residual + row L2 normalize (col0 == 0, N == 128)
        float* zs = smem;  // reuse pipeline smem: 128 x ZS
#pragma unroll
        for (int mt = 0; mt < 2; mt++)
#pragma unroll
            for (int nt = 0; nt < 8; nt++) {
                int c = wn * 64 + nt * 8 + 2 * t4c;
                float bb0 = bias[c], bb1 = bias[c + 1];
#pragma unroll
                for (int half = 0; half < 2; half++) {
                    int rl = wm * 32 + mt * 16 + t4r + half * 8;
                    int r = row0 + rl;
                    if (r >= M) continue;
                    float2 rv = *(const float2*)&res[(size_t)r * DIM + c];
                    zs[rl * ZS + c]     = acc[mt][nt][half * 2 + 0] + bb0 + rv.x;
                    zs[rl * ZS + c + 1] = acc[mt][nt][half * 2 + 1] + bb1 + rv.y;
                }
            }
        __syncthreads();
#pragma unroll
        for (int rr = 0; rr < 16; rr++) {
            int rl = wid * 16 + rr;
            int r = row0 + rl;
            if (r >= M) continue;
            float4 z = *(float4*)&zs[rl * ZS + lane * 4];
            float ss = warp_sum(z.x * z.x + z.y * z.y + z.z * z.z + z.w * z.w);
            float inv = 1.f / fmaxf(sqrtf(ss), 1e-12f);
            float4 o = {z.x * inv, z.y * inv, z.z * inv, z.w * inv};
            *(float4*)&Cout[(size_t)r * DIM + lane * 4] = o;
        }
    }
}

// ---------------- sorted aggregation: warp per dst node (fp16 h) ------------
__global__ void k_aggsort(int N, const float* __restrict__ gat_bias) {
    int gid = blockIdx.x * blockDim.x + threadIdx.x;
    int n = gid >> 5;
    if (n >= N) return;
    int lane = gid & 31;
    int h = lane >> 2;
    int off = g_offi[n], cnt = g_indeg[n];
    float ad = g_ad[n * 8 + h];

    float4 acc = make_float4(0.f, 0.f, 0.f, 0.f);
    float den = 0.f;

    int i = 0;
    for (; i + 2 <= cnt; i += 2) {
        int s0 = __ldg(&g_ssrc[off + i]);
        int s1 = __ldg(&g_ssrc[off + i + 1]);
        float as0 = __ldg(&g_as[s0 * 8 + h]);
        float as1 = __ldg(&g_as[s1 * 8 + h]);
        uint2 r0 = __ldg((const uint2*)&g_hh[(size_t)s0 * DIM + lane * 4]);
        uint2 r1 = __ldg((const uint2*)&g_hh[(size_t)s1 * DIM + lane * 4]);
        float2 h0a = __half22float2(*(__half2*)&r0.x);
        float2 h0b = __half22float2(*(__half2*)&r0.y);
        float2 h1a = __half22float2(*(__half2*)&r1.x);
        float2 h1b = __half22float2(*(__half2*)&r1.y);
        float v0 = as0 + ad; v0 = v0 > 0.f ? v0 : 0.2f * v0;
        float v1 = as1 + ad; v1 = v1 > 0.f ? v1 : 0.2f * v1;
        float w0 = (s0 == n) ? 0.f : __expf(v0);
        float w1 = (s1 == n) ? 0.f : __expf(v1);
        den += w0 + w1;
        acc.x += w0 * h0a.x + w1 * h1a.x;
        acc.y += w0 * h0a.y + w1 * h1a.y;
        acc.z += w0 * h0b.x + w1 * h1b.x;
        acc.w += w0 * h0b.y + w1 * h1b.y;
    }
    if (i < cnt) {
        int s0 = __ldg(&g_ssrc[off + i]);
        float as0 = __ldg(&g_as[s0 * 8 + h]);
        uint2 r0 = __ldg((const uint2*)&g_hh[(size_t)s0 * DIM + lane * 4]);
        float2 h0a = __half22float2(*(__half2*)&r0.x);
        float2 h0b = __half22float2(*(__half2*)&r0.y);
        float v0 = as0 + ad; v0 = v0 > 0.f ? v0 : 0.2f * v0;
        float w0 = (s0 == n) ? 0.f : __expf(v0);
        den += w0;
        acc.x += w0 * h0a.x; acc.y += w0 * h0a.y;
        acc.z += w0 * h0b.x; acc.w += w0 * h0b.y;
    }

    // self loop
    float asn = g_as[n * 8 + h];
    float vs = asn + ad; vs = vs > 0.f ? vs : 0.2f * vs;
    float ws = __expf(vs);
    uint2 rn = __ldg((const uint2*)&g_hh[(size_t)n * DIM + lane * 4]);
    float2 hna = __half22float2(*(__half2*)&rn.x);
    float2 hnb = __half22float2(*(__half2*)&rn.y);
    den += ws;
    acc.x += ws * hna.x; acc.y += ws * hna.y;
    acc.z += ws * hnb.x; acc.w += ws * hnb.y;

    float inv = 1.f / (den + 1e-16f);
    float4 b = ((const float4*)gat_bias)[lane];
    float4 y;
    y.x = acc.x * inv + b.x;
    y.y = acc.y * inv + b.y;
    y.z = acc.z * inv + b.z;
    y.w = acc.w * inv + b.w;
    ((float4*)g_agg)[(size_t)n * 32 + lane] = y;

    float sum = warp_sum(y.x + y.y + y.z + y.w);
    if (lane == 0) {
        float di = rsqrtf((float)g_outdeg[n] + 1e-6f);
        g_di[n] = di;
        g_p[n] = di * sum * (1.f / 128.f);
    }
}

// ---------------- laplacian pass 1: mean gather + q -------------------------
__global__ void k_lap1(int N) {
    int gid = blockIdx.x * blockDim.x + threadIdx.x;
    int n = gid >> 5;
    if (n >= N) return;
    int lane = gid & 31;
    int off = g_offo[n], cnt = g_outdeg[n];
    float s = 0.f;
    for (int i = lane; i < cnt; i += 32)
        s += __ldg(&g_p[__ldg(&g_sdst[off + i])]);
    s = warp_sum(s);
    float di = g_di[n];
    float mean = di * s;
    float4 y = ((const float4*)g_agg)[(size_t)n * 32 + lane];
    float a0 = y.x - mean, a1 = y.y - mean, a2 = y.z - mean, a3 = y.w - mean;
    float ss = warp_sum(a0 * a0 + a1 * a1 + a2 * a2 + a3 * a3);
    if (lane == 0) {
        g_mean[n] = mean;
        g_pq[n] = di * ss * (1.f / 128.f);
    }
}

// ---------------- laplacian pass 2: var gather + LapNorm + res + LayerNorm --
__global__ void k_lap2(int N, const float* __restrict__ x,
                       const float* __restrict__ s1, const float* __restrict__ b1,
                       const float* __restrict__ s2, const float* __restrict__ b2) {
    int gid = blockIdx.x * blockDim.x + threadIdx.x;
    int n = gid >> 5;
    if (n >= N) return;
    int lane = gid & 31;
    int off = g_offo[n], cnt = g_outdeg[n];
    float s = 0.f;
    for (int i = lane; i < cnt; i += 32)
        s += __ldg(&g_pq[__ldg(&g_sdst[off + i])]);
    s = warp_sum(s);
    float var = g_di[n] * s;
    float m = g_mean[n];
    float inv1 = 1.f / sqrtf(var + 1e-6f);

    float4 y = ((const float4*)g_agg)[(size_t)n * 32 + lane];
    float4 xv = ((const float4*)x)[(size_t)n * 32 + lane];
    float4 sc1 = ((const float4*)s1)[lane];
    float4 bb1 = ((const float4*)b1)[lane];
    float4 sc2 = ((const float4*)s2)[lane];
    float4 bb2 = ((const float4*)b2)[lane];
    float o0 = (y.x - m) * inv1 * sc1.x + bb1.x + xv.x;
    float o1 = (y.y - m) * inv1 * sc1.y + bb1.y + xv.y;
    float o2 = (y.z - m) * inv1 * sc1.z + bb1.z + xv.z;
    float o3 = (y.w - m) * inv1 * sc1.w + bb1.w + xv.w;
    float mu = warp_sum(o0 + o1 + o2 + o3) * (1.f / 128.f);
    float c0 = o0 - mu, c1 = o1 - mu, c2 = o2 - mu, c3 = o3 - mu;
    float vs = warp_sum(c0 * c0 + c1 * c1 + c2 * c2 + c3 * c3);
    float inv2 = rsqrtf(vs * (1.f / 128.f) + 1e-5f);
    float4 r;
    r.x = c0 * inv2 * sc2.x + bb2.x;
    r.y = c1 * inv2 * sc2.y + bb2.y;
    r.z = c2 * inv2 * sc2.z + bb2.z;
    r.w = c3 * inv2 * sc2.w + bb2.w;
    ((float4*)g_ln)[(size_t)n * 32 + lane] = r;
}

// ---------------- launch ----------------------------------------------------
extern "C" void kernel_launch(void* const* d_in, const int* in_sizes, int n_in,
                              void* d_out, int out_size) {
    const float* x        = (const float*)d_in[0];
    const int* ei         = (const int*)d_in[1];
    const float* W        = (const float*)d_in[2];
    const float* att_src  = (const float*)d_in[3];
    const float* att_dst  = (const float*)d_in[4];
    const float* gat_bias = (const float*)d_in[5];
    const float* ln1s     = (const float*)d_in[6];
    const float* ln1b     = (const float*)d_in[7];
    const float* ln2s     = (const float*)d_in[8];
    const float* ln2b     = (const float*)d_in[9];
    const float* W1       = (const float*)d_in[10];
    const float* b1       = (const float*)d_in[11];
    const float* W2       = (const float*)d_in[12];
    const float* b2       = (const float*)d_in[13];
    float* out            = (float*)d_out;

    int N = in_sizes[0] / DIM;
    int E = in_sizes[1] / 2;
    int nb = (N + SCANB - 1) / SCANB;
    int mb = (N + 127) / 128;

    float *p_ln, *p_t;
    cudaGetSymbolAddress((void**)&p_ln, g_ln);
    cudaGetSymbolAddress((void**)&p_t, g_t);

    cudaFuncSetAttribute(k_gemm_tc<1>, cudaFuncAttributeMaxDynamicSharedMemorySize, GEMM_SMEM);
    cudaFuncSetAttribute(k_gemm_tc<3>, cudaFuncAttributeMaxDynamicSharedMemorySize, GEMM_SMEM);
    cudaFuncSetAttribute(k_gemm_tc<4>, cudaFuncAttributeMaxDynamicSharedMemorySize, GEMM_SMEM);

    // fork: CSR build on side stream, GEMM-0 on main (capturing) stream
    cudaStream_t s2;
    cudaEvent_t evA, evB;
    cudaStreamCreateWithFlags(&s2, cudaStreamNonBlocking);
    cudaEventCreateWithFlags(&evA, cudaEventDisableTiming);
    cudaEventCreateWithFlags(&evB, cudaEventDisableTiming);

    cudaEventRecord(evA, 0);
    cudaStreamWaitEvent(s2, evA, 0);

    // CSR build (side stream)
    k_init<<<(N + 255) / 256, 256, 0, s2>>>(N);
    k_edge0<<<(E + 255) / 256, 256, 0, s2>>>(ei, E);
    k_scan1<<<nb, 256, 0, s2>>>(N);
    k_scan3<<<nb, 256, 0, s2>>>(N, nb);
    k_scatter<<<(E + 255) / 256, 256, 0, s2>>>(ei, E);
    cudaEventRecord(evB, s2);

    // h = x @ W (+ fused attention dots) on main stream
    k_gemm_tc<3><<<dim3(1, mb), 256, GEMM_SMEM>>>(N, DIM, DIM, x, W, nullptr, nullptr,
                                                  nullptr, att_src, att_dst);

    // join
    cudaStreamWaitEvent(0, evB, 0);

    // sorted aggregation + GAT finalize + p
    k_aggsort<<<(N * 32 + 255) / 256, 256>>>(N, gat_bias);

    // laplacian passes (gather-based) + fused LN
    k_lap1<<<(N * 32 + 255) / 256, 256>>>(N);
    k_lap2<<<(N * 32 + 255) / 256, 256>>>(N, x, ln1s, ln1b, ln2s, ln2b);

    // MLP (+ fused final L2 normalize)
    k_gemm_tc<1><<<dim3(2, mb), 256, GEMM_SMEM>>>(N, 2 * DIM, DIM, p_ln, W1, b1, nullptr,
                                                  p_t, nullptr, nullptr);
    k_gemm_tc<4><<<dim3(1, mb), 256, GEMM_SMEM>>>(N, DIM, 2 * DIM, p_t, W2, b2, p_ln,
                                                  out, nullptr, nullptr);
}

// round 8
// speedup vs baseline: 4.2336x; 1.1899x over previous
#include <cuda_runtime.h>
#include <cuda_fp16.h>
#include <stdint.h>
#include <math.h>

#define MAXN 50000
#define MAXE 800000
#define DIM 128
#define NH 8
#define SCANB 1024
#define MAXBLK 64

// ---------------- scratch (static device globals; no allocation) ------------
__device__ __half g_hh[MAXN * DIM];      // h = x @ W (fp16)
__device__ float g_as[MAXN * NH];
__device__ float g_ad[MAXN * NH];
__device__ float g_agg[MAXN * DIM];      // GAT output y
__device__ float g_di[MAXN];
__device__ float g_p[MAXN];
__device__ float g_pq[MAXN];
__device__ float g_mean[MAXN];
__device__ float g_ln[MAXN * DIM];       // LN output fp32 (residual for gemm2)
__device__ __half g_lnh[MAXN * DIM];     // LN output fp16 (A of gemm1)
__device__ __half g_th[MAXN * 2 * DIM];  // GELU intermediate fp16 (A of gemm2)
__device__ int   g_indeg[MAXN];
__device__ int   g_outdeg[MAXN];
__device__ int   g_cin[MAXN];
__device__ int   g_cout[MAXN];
__device__ int   g_offi[MAXN];
__device__ int   g_offo[MAXN];
__device__ int   g_ssrc[MAXE];
__device__ int   g_sdst[MAXE];
__device__ int   g_bsum_i[MAXBLK];
__device__ int   g_bsum_o[MAXBLK];
// fp16 transposed weights [n][k]
__device__ __half g_w0[128 * 128];
__device__ __half g_w1[256 * 128];
__device__ __half g_w2[128 * 256];

// ---------------- helpers ---------------------------------------------------
__device__ __forceinline__ uint32_t smem_u32(const void* p) {
    uint32_t a;
    asm("{ .reg .u64 t; cvta.to.shared.u64 t, %1; cvt.u32.u64 %0, t; }"
        : "=r"(a) : "l"(p));
    return a;
}
__device__ __forceinline__ void ldsm_x4(uint32_t& r0, uint32_t& r1, uint32_t& r2,
                                        uint32_t& r3, uint32_t addr) {
    asm volatile("ldmatrix.sync.aligned.m8n8.x4.shared.b16 {%0,%1,%2,%3}, [%4];"
                 : "=r"(r0), "=r"(r1), "=r"(r2), "=r"(r3) : "r"(addr));
}
__device__ __forceinline__ void mma16816(float* c, const uint32_t* a, uint32_t b0, uint32_t b1) {
    asm volatile(
        "mma.sync.aligned.m16n8k16.row.col.f32.f16.f16.f32 "
        "{%0,%1,%2,%3}, {%4,%5,%6,%7}, {%8,%9}, {%0,%1,%2,%3};"
        : "+f"(c[0]), "+f"(c[1]), "+f"(c[2]), "+f"(c[3])
        : "r"(a[0]), "r"(a[1]), "r"(a[2]), "r"(a[3]), "r"(b0), "r"(b1));
}
__device__ __forceinline__ void cp16(void* dst_smem, const void* src, bool pred) {
    unsigned d = (unsigned)__cvta_generic_to_shared(dst_smem);
    int sz = pred ? 16 : 0;
    asm volatile("cp.async.cg.shared.global [%0], [%1], 16, %2;\n" :: "r"(d), "l"(src), "r"(sz));
}
__device__ __forceinline__ void cp_commit() { asm volatile("cp.async.commit_group;\n"); }
template <int NW>
__device__ __forceinline__ void cp_wait() { asm volatile("cp.async.wait_group %0;\n" :: "n"(NW)); }

__device__ __forceinline__ float gelu_exact(float v) {
    return 0.5f * v * (1.0f + erff(v * 0.7071067811865476f));
}
__device__ __forceinline__ float warp_sum(float s) {
#pragma unroll
    for (int o = 16; o > 0; o >>= 1) s += __shfl_xor_sync(0xffffffffu, s, o);
    return s;
}
__device__ __forceinline__ uint32_t packh2(float a, float b) {
    __half2 h = __floats2half2_rn(a, b);
    return *(uint32_t*)&h;
}

// ---------------- weight prep: transpose + fp16 ------------------------------
__global__ void k_prepW(const float* __restrict__ W, const float* __restrict__ W1,
                        const float* __restrict__ W2) {
    int i = blockIdx.x * blockDim.x + threadIdx.x;
    if (i < 16384) {
        int n = i >> 7, k = i & 127;
        g_w0[i] = __float2half_rn(W[k * 128 + n]);
    } else if (i < 49152) {
        int j = i - 16384;
        int n = j >> 7, k = j & 127;
        g_w1[j] = __float2half_rn(W1[k * 256 + n]);
    } else if (i < 81920) {
        int j = i - 49152;
        int n = j >> 8, k = j & 255;
        g_w2[j] = __float2half_rn(W2[k * 128 + n]);
    }
}

// ---------------- init / histograms / scan / scatter ------------------------
__global__ void k_init(int N) {
    int i = blockIdx.x * blockDim.x + threadIdx.x;
    if (i < N) { g_indeg[i] = 0; g_outdeg[i] = 0; g_cin[i] = 0; g_cout[i] = 0; }
}
__global__ void k_edge0(const int* __restrict__ ei, int E) {
    int e = blockIdx.x * blockDim.x + threadIdx.x;
    if (e >= E) return;
    atomicAdd(&g_outdeg[ei[e]], 1);
    atomicAdd(&g_indeg[ei[E + e]], 1);
}
__global__ void k_scan1(int N) {
    __shared__ int smi[256], smo[256];
    int base = blockIdx.x * SCANB + threadIdx.x * 4;
    int ti = 0, to = 0;
#pragma unroll
    for (int j = 0; j < 4; j++)
        if (base + j < N) { ti += g_indeg[base + j]; to += g_outdeg[base + j]; }
    smi[threadIdx.x] = ti; smo[threadIdx.x] = to;
    __syncthreads();
    for (int o = 128; o > 0; o >>= 1) {
        if (threadIdx.x < o) { smi[threadIdx.x] += smi[threadIdx.x + o];
                               smo[threadIdx.x] += smo[threadIdx.x + o]; }
        __syncthreads();
    }
    if (threadIdx.x == 0) { g_bsum_i[blockIdx.x] = smi[0]; g_bsum_o[blockIdx.x] = smo[0]; }
}
__global__ void k_scan3(int N, int nb) {
    __shared__ int smi[256], smo[256];
    __shared__ int sbi[MAXBLK], sbo[MAXBLK];
    __shared__ int basei, baseo;
    int tid = threadIdx.x;
    if (tid < nb) { sbi[tid] = g_bsum_i[tid]; sbo[tid] = g_bsum_o[tid]; }
    __syncthreads();
    if (tid == 0) {
        int bi = 0, bo = 0;
        for (int b = 0; b < (int)blockIdx.x; b++) { bi += sbi[b]; bo += sbo[b]; }
        basei = bi; baseo = bo;
    }
    int base = blockIdx.x * SCANB + tid * 4;
    int vi[4] = {0,0,0,0}, vo[4] = {0,0,0,0};
#pragma unroll
    for (int j = 0; j < 4; j++)
        if (base + j < N) { vi[j] = g_indeg[base + j]; vo[j] = g_outdeg[base + j]; }
    int tsi = vi[0]+vi[1]+vi[2]+vi[3], tso = vo[0]+vo[1]+vo[2]+vo[3];
    smi[tid] = tsi; smo[tid] = tso;
    __syncthreads();
    for (int o = 1; o < 256; o <<= 1) {
        int a = (tid >= o) ? smi[tid - o] : 0;
        int b = (tid >= o) ? smo[tid - o] : 0;
        __syncthreads();
        smi[tid] += a; smo[tid] += b;
        __syncthreads();
    }
    int gi = basei + smi[tid] - tsi;
    int go = baseo + smo[tid] - tso;
#pragma unroll
    for (int j = 0; j < 4; j++) {
        if (base + j < N) { g_offi[base + j] = gi; g_offo[base + j] = go; }
        gi += vi[j]; go += vo[j];
    }
}
__global__ void k_scatter(const int* __restrict__ ei, int E) {
    int e = blockIdx.x * blockDim.x + threadIdx.x;
    if (e >= E) return;
    int s = ei[e], d = ei[E + e];
    g_ssrc[g_offi[d] + atomicAdd(&g_cin[d], 1)] = s;
    g_sdst[g_offo[s] + atomicAdd(&g_cout[s], 1)] = d;
}

// ---------------- fp16 mma GEMM with ldmatrix --------------------------------
// Tile 128x128, K chunked by 128. 256 threads = 8 warps (4m x 2n), warp 32x64.
// A: [m][Ktot] fp32 (AHALF=0, convert at stage) or fp16 (AHALF=1, cp.async).
// B: [n][Ktot] fp16 (col-major for mma.row.col).
// ACT: 1 = bias+GELU -> fp16 Cout16 (stride 256)
//      3 = fp16 h store + fused attention dots
//      4 = bias + residual + row-L2-normalize -> fp32 Cout (stride 128)
#define SAH 136                       // half stride (272 B/row, ldmatrix conflict-free)
#define FMMA_SMEM (2 * 128 * SAH * 2) // A tile + B tile, fp16
#define ZS 132

template <int ACT, int AHALF>
__global__ __launch_bounds__(256) void k_fmma(
        int M, int Ktot,
        const void* __restrict__ Ain,
        const __half* __restrict__ B,
        const float* __restrict__ bias,
        const float* __restrict__ res,
        float* __restrict__ Cout,
        __half* __restrict__ Cout16,
        const float* __restrict__ asrc,
        const float* __restrict__ adst) {
    extern __shared__ __align__(16) char smem[];
    __half* sA = (__half*)smem;                  // 128 x SAH
    __half* sB = (__half*)smem + 128 * SAH;      // 128 x SAH
    uint32_t sA32 = smem_u32(sA), sB32 = smem_u32(sB);

    int tid = threadIdx.x, wid = tid >> 5, lane = tid & 31;
    int row0 = blockIdx.y * 128, col0 = blockIdx.x * 128;
    int wm = wid & 3, wn = wid >> 2;
    int t4r = lane >> 2, t4c = lane & 3;

    float acc[2][8][4];
#pragma unroll
    for (int mt = 0; mt < 2; mt++)
#pragma unroll
        for (int nt = 0; nt < 8; nt++)
#pragma unroll
            for (int i = 0; i < 4; i++) acc[mt][nt][i] = 0.f;

    int T = Ktot >> 7;
    for (int kc = 0; kc < T; kc++) {
        int k0 = kc << 7;
        if (kc > 0) __syncthreads();  // previous compute done before overwrite
        // B tile: 128 rows x 128 halves, cp.async
#pragma unroll
        for (int j = 0; j < 8; j++) {
            int idx = tid + j * 256;
            int n = idx >> 4, g = (idx & 15) << 3;
            cp16(&sB[n * SAH + g], &B[(size_t)(col0 + n) * Ktot + k0 + g], true);
        }
        // A tile
        if (AHALF) {
            const __half* Ah = (const __half*)Ain;
#pragma unroll
            for (int j = 0; j < 8; j++) {
                int idx = tid + j * 256;
                int r = idx >> 4, g = (idx & 15) << 3;
                cp16(&sA[r * SAH + g], &Ah[(size_t)(row0 + r) * Ktot + k0 + g],
                     row0 + r < M);
            }
            cp_commit();
            cp_wait<0>();
        } else {
            cp_commit();
            const float* Af = (const float*)Ain;
#pragma unroll
            for (int j = 0; j < 8; j++) {
                int idx = tid + j * 256;
                int r = idx >> 4, g = (idx & 15) << 3;
                uint4 o = {0, 0, 0, 0};
                if (row0 + r < M) {
                    const float* ap = &Af[(size_t)(row0 + r) * Ktot + k0 + g];
                    float4 v0 = *(const float4*)ap;
                    float4 v1 = *(const float4*)(ap + 4);
                    o.x = packh2(v0.x, v0.y);
                    o.y = packh2(v0.z, v0.w);
                    o.z = packh2(v1.x, v1.y);
                    o.w = packh2(v1.z, v1.w);
                }
                *(uint4*)&sA[r * SAH + g] = o;
            }
            cp_wait<0>();
        }
        __syncthreads();

        // compute: 8 k16 steps
#pragma unroll
        for (int kk = 0; kk < 128; kk += 16) {
            uint32_t af[2][4];
#pragma unroll
            for (int mt = 0; mt < 2; mt++) {
                int r = wm * 32 + mt * 16 + (lane & 15);
                uint32_t addr = sA32 + r * (SAH * 2) + kk * 2 + (lane >> 4) * 16;
                ldsm_x4(af[mt][0], af[mt][1], af[mt][2], af[mt][3], addr);
            }
            uint32_t bf[8][2];
#pragma unroll
            for (int nb = 0; nb < 4; nb++) {
                int n = wn * 64 + nb * 16 + (lane & 15);
                uint32_t addr = sB32 + n * (SAH * 2) + kk * 2 + (lane >> 4) * 16;
                uint32_t q0, q1, q2, q3;
                ldsm_x4(q0, q1, q2, q3, addr);
                bf[nb * 2][0] = q0; bf[nb * 2 + 1][0] = q1;
                bf[nb * 2][1] = q2; bf[nb * 2 + 1][1] = q3;
            }
#pragma unroll
            for (int mt = 0; mt < 2; mt++)
#pragma unroll
                for (int nt = 0; nt < 8; nt++)
                    mma16816(acc[mt][nt], af[mt], bf[nt][0], bf[nt][1]);
        }
    }

    // ---------------- epilogues ----------------
    if (ACT == 1) {
#pragma unroll
        for (int mt = 0; mt < 2; mt++)
#pragma unroll
            for (int nt = 0; nt < 8; nt++) {
                int c = col0 + wn * 64 + nt * 8 + 2 * t4c;
                float bb0 = bias[c], bb1 = bias[c + 1];
#pragma unroll
                for (int half = 0; half < 2; half++) {
                    int r = row0 + wm * 32 + mt * 16 + t4r + half * 8;
                    if (r >= M) continue;
                    uint32_t o = packh2(gelu_exact(acc[mt][nt][half * 2 + 0] + bb0),
                                        gelu_exact(acc[mt][nt][half * 2 + 1] + bb1));
                    *(uint32_t*)&Cout16[(size_t)r * 256 + c] = o;
                }
            }
    } else if (ACT == 3) {
        // fp16 h store + attention dots (col0 == 0)
#pragma unroll
        for (int mt = 0; mt < 2; mt++)
#pragma unroll
            for (int half = 0; half < 2; half++) {
                int r = row0 + wm * 32 + mt * 16 + t4r + half * 8;
                bool ok = r < M;
                float pa[4] = {0,0,0,0}, pd[4] = {0,0,0,0};
#pragma unroll
                for (int nt = 0; nt < 8; nt++) {
                    int c = wn * 64 + nt * 8 + 2 * t4c;
                    float v0 = acc[mt][nt][half * 2 + 0];
                    float v1 = acc[mt][nt][half * 2 + 1];
                    if (ok) *(uint32_t*)&g_hh[(size_t)r * DIM + c] = packh2(v0, v1);
                    int p = nt >> 1;
                    pa[p] += v0 * __ldg(&asrc[c]) + v1 * __ldg(&asrc[c + 1]);
                    pd[p] += v0 * __ldg(&adst[c]) + v1 * __ldg(&adst[c + 1]);
                }
#pragma unroll
                for (int p = 0; p < 4; p++) {
                    pa[p] += __shfl_xor_sync(0xffffffffu, pa[p], 1);
                    pa[p] += __shfl_xor_sync(0xffffffffu, pa[p], 2);
                    pd[p] += __shfl_xor_sync(0xffffffffu, pd[p], 1);
                    pd[p] += __shfl_xor_sync(0xffffffffu, pd[p], 2);
                }
                if (ok && t4c == 0) {
#pragma unroll
                    for (int p = 0; p < 4; p++) {
                        g_as[r * NH + wn * 4 + p] = pa[p];
                        g_ad[r * NH + wn * 4 + p] = pd[p];
                    }
                }
            }
    } else {  // ACT == 4: bias + residual + row-L2-normalize (col0 == 0)
        float* zs = (float*)smem;  // 128 x ZS floats
        __syncthreads();           // compute done; smem reusable
#pragma unroll
        for (int mt = 0; mt < 2; mt++)
#pragma unroll
            for (int nt = 0; nt < 8; nt++) {
                int c = wn * 64 + nt * 8 + 2 * t4c;
                float bb0 = bias[c], bb1 = bias[c + 1];
#pragma unroll
                for (int half = 0; half < 2; half++) {
                    int rl = wm * 32 + mt * 16 + t4r + half * 8;
                    int r = row0 + rl;
                    if (r >= M) continue;
                    float2 rv = *(const float2*)&res[(size_t)r * DIM + c];
                    zs[rl * ZS + c]     = acc[mt][nt][half * 2 + 0] + bb0 + rv.x;
                    zs[rl * ZS + c + 1] = acc[mt][nt][half * 2 + 1] + bb1 + rv.y;
                }
            }
        __syncthreads();
#pragma unroll
        for (int rr = 0; rr < 16; rr++) {
            int rl = wid * 16 + rr;
            int r = row0 + rl;
            if (r >= M) continue;
            float4 z = *(float4*)&zs[rl * ZS + lane * 4];
            float ss = warp_sum(z.x * z.x + z.y * z.y + z.z * z.z + z.w * z.w);
            float inv = 1.f / fmaxf(sqrtf(ss), 1e-12f);
            float4 o = {z.x * inv, z.y * inv, z.z * inv, z.w * inv};
            *(float4*)&Cout[(size_t)r * DIM + lane * 4] = o;
        }
    }
}

// ---------------- sorted aggregation: warp per dst node (fp16 h) ------------
__global__ void k_aggsort(int N, const float* __restrict__ gat_bias) {
    int gid = blockIdx.x * blockDim.x + threadIdx.x;
    int n = gid >> 5;
    if (n >= N) return;
    int lane = gid & 31;
    int h = lane >> 2;
    int off = g_offi[n], cnt = g_indeg[n];
    float ad = g_ad[n * 8 + h];

    float4 acc = make_float4(0.f, 0.f, 0.f, 0.f);
    float den = 0.f;

    int i = 0;
    for (; i + 4 <= cnt; i += 4) {
        int s0 = __ldg(&g_ssrc[off + i]);
        int s1 = __ldg(&g_ssrc[off + i + 1]);
        int s2 = __ldg(&g_ssrc[off + i + 2]);
        int s3 = __ldg(&g_ssrc[off + i + 3]);
        float as0 = __ldg(&g_as[s0 * 8 + h]);
        float as1 = __ldg(&g_as[s1 * 8 + h]);
        float as2 = __ldg(&g_as[s2 * 8 + h]);
        float as3 = __ldg(&g_as[s3 * 8 + h]);
        uint2 r0 = __ldg((const uint2*)&g_hh[(size_t)s0 * DIM + lane * 4]);
        uint2 r1 = __ldg((const uint2*)&g_hh[(size_t)s1 * DIM + lane * 4]);
        uint2 r2 = __ldg((const uint2*)&g_hh[(size_t)s2 * DIM + lane * 4]);
        uint2 r3 = __ldg((const uint2*)&g_hh[(size_t)s3 * DIM + lane * 4]);
        float v0 = as0 + ad; v0 = v0 > 0.f ? v0 : 0.2f * v0;
        float v1 = as1 + ad; v1 = v1 > 0.f ? v1 : 0.2f * v1;
        float v2 = as2 + ad; v2 = v2 > 0.f ? v2 : 0.2f * v2;
        float v3 = as3 + ad; v3 = v3 > 0.f ? v3 : 0.2f * v3;
        float w0 = (s0 == n) ? 0.f : __expf(v0);
        float w1 = (s1 == n) ? 0.f : __expf(v1);
        float w2 = (s2 == n) ? 0.f : __expf(v2);
        float w3 = (s3 == n) ? 0.f : __expf(v3);
        den += (w0 + w1) + (w2 + w3);
        float2 a0 = __half22float2(*(__half2*)&r0.x), b0 = __half22float2(*(__half2*)&r0.y);
        float2 a1 = __half22float2(*(__half2*)&r1.x), b1 = __half22float2(*(__half2*)&r1.y);
        float2 a2 = __half22float2(*(__half2*)&r2.x), b2 = __half22float2(*(__half2*)&r2.y);
        float2 a3 = __half22float2(*(__half2*)&r3.x), b3 = __half22float2(*(__half2*)&r3.y);
        acc.x += w0 * a0.x + w1 * a1.x + w2 * a2.x + w3 * a3.x;
        acc.y += w0 * a0.y + w1 * a1.y + w2 * a2.y + w3 * a3.y;
        acc.z += w0 * b0.x + w1 * b1.x + w2 * b2.x + w3 * b3.x;
        acc.w += w0 * b0.y + w1 * b1.y + w2 * b2.y + w3 * b3.y;
    }
    for (; i < cnt; i++) {
        int s0 = __ldg(&g_ssrc[off + i]);
        float as0 = __ldg(&g_as[s0 * 8 + h]);
        uint2 r0 = __ldg((const uint2*)&g_hh[(size_t)s0 * DIM + lane * 4]);
        float2 a0 = __half22float2(*(__half2*)&r0.x), b0 = __half22float2(*(__half2*)&r0.y);
        float v0 = as0 + ad; v0 = v0 > 0.f ? v0 : 0.2f * v0;
        float w0 = (s0 == n) ? 0.f : __expf(v0);
        den += w0;
        acc.x += w0 * a0.x; acc.y += w0 * a0.y;
        acc.z += w0 * b0.x; acc.w += w0 * b0.y;
    }

    // self loop
    float asn = g_as[n * 8 + h];
    float vs = asn + ad; vs = vs > 0.f ? vs : 0.2f * vs;
    float ws = __expf(vs);
    uint2 rn = __ldg((const uint2*)&g_hh[(size_t)n * DIM + lane * 4]);
    float2 hna = __half22float2(*(__half2*)&rn.x);
    float2 hnb = __half22float2(*(__half2*)&rn.y);
    den += ws;
    acc.x += ws * hna.x; acc.y += ws * hna.y;
    acc.z += ws * hnb.x; acc.w += ws * hnb.y;

    float inv = 1.f / (den + 1e-16f);
    float4 b = ((const float4*)gat_bias)[lane];
    float4 y;
    y.x = acc.x * inv + b.x;
    y.y = acc.y * inv + b.y;
    y.z = acc.z * inv + b.z;
    y.w = acc.w * inv + b.w;
    ((float4*)g_agg)[(size_t)n * 32 + lane] = y;

    float sum = warp_sum(y.x + y.y + y.z + y.w);
    if (lane == 0) {
        float di = rsqrtf((float)g_outdeg[n] + 1e-6f);
        g_di[n] = di;
        g_p[n] = di * sum * (1.f / 128.f);
    }
}

// ---------------- laplacian passes -------------------------------------------
__global__ void k_lap1(int N) {
    int gid = blockIdx.x * blockDim.x + threadIdx.x;
    int n = gid >> 5;
    if (n >= N) return;
    int lane = gid & 31;
    int off = g_offo[n], cnt = g_outdeg[n];
    float s = 0.f;
    for (int i = lane; i < cnt; i += 32)
        s += __ldg(&g_p[__ldg(&g_sdst[off + i])]);
    s = warp_sum(s);
    float di = g_di[n];
    float mean = di * s;
    float4 y = ((const float4*)g_agg)[(size_t)n * 32 + lane];
    float a0 = y.x - mean, a1 = y.y - mean, a2 = y.z - mean, a3 = y.w - mean;
    float ss = warp_sum(a0 * a0 + a1 * a1 + a2 * a2 + a3 * a3);
    if (lane == 0) {
        g_mean[n] = mean;
        g_pq[n] = di * ss * (1.f / 128.f);
    }
}

__global__ void k_lap2(int N, const float* __restrict__ x,
                       const float* __restrict__ s1, const float* __restrict__ b1,
                       const float* __restrict__ s2, const float* __restrict__ b2) {
    int gid = blockIdx.x * blockDim.x + threadIdx.x;
    int n = gid >> 5;
    if (n >= N) return;
    int lane = gid & 31;
    int off = g_offo[n], cnt = g_outdeg[n];
    float s = 0.f;
    for (int i = lane; i < cnt; i += 32)
        s += __ldg(&g_pq[__ldg(&g_sdst[off + i])]);
    s = warp_sum(s);
    float var = g_di[n] * s;
    float m = g_mean[n];
    float inv1 = 1.f / sqrtf(var + 1e-6f);

    float4 y = ((const float4*)g_agg)[(size_t)n * 32 + lane];
    float4 xv = ((const float4*)x)[(size_t)n * 32 + lane];
    float4 sc1 = ((const float4*)s1)[lane];
    float4 bb1 = ((const float4*)b1)[lane];
    float4 sc2 = ((const float4*)s2)[lane];
    float4 bb2 = ((const float4*)b2)[lane];
    float o0 = (y.x - m) * inv1 * sc1.x + bb1.x + xv.x;
    float o1 = (y.y - m) * inv1 * sc1.y + bb1.y + xv.y;
    float o2 = (y.z - m) * inv1 * sc1.z + bb1.z + xv.z;
    float o3 = (y.w - m) * inv1 * sc1.w + bb1.w + xv.w;
    float mu = warp_sum(o0 + o1 + o2 + o3) * (1.f / 128.f);
    float c0 = o0 - mu, c1 = o1 - mu, c2 = o2 - mu, c3 = o3 - mu;
    float vs = warp_sum(c0 * c0 + c1 * c1 + c2 * c2 + c3 * c3);
    float inv2 = rsqrtf(vs * (1.f / 128.f) + 1e-5f);
    float4 r;
    r.x = c0 * inv2 * sc2.x + bb2.x;
    r.y = c1 * inv2 * sc2.y + bb2.y;
    r.z = c2 * inv2 * sc2.z + bb2.z;
    r.w = c3 * inv2 * sc2.w + bb2.w;
    ((float4*)g_ln)[(size_t)n * 32 + lane] = r;
    uint2 ho;
    ho.x = packh2(r.x, r.y);
    ho.y = packh2(r.z, r.w);
    *(uint2*)&g_lnh[(size_t)n * DIM + lane * 4] = ho;
}

// ---------------- launch ----------------------------------------------------
extern "C" void kernel_launch(void* const* d_in, const int* in_sizes, int n_in,
                              void* d_out, int out_size) {
    const float* x        = (const float*)d_in[0];
    const int* ei         = (const int*)d_in[1];
    const float* W        = (const float*)d_in[2];
    const float* att_src  = (const float*)d_in[3];
    const float* att_dst  = (const float*)d_in[4];
    const float* gat_bias = (const float*)d_in[5];
    const float* ln1s     = (const float*)d_in[6];
    const float* ln1b     = (const float*)d_in[7];
    const float* ln2s     = (const float*)d_in[8];
    const float* ln2b     = (const float*)d_in[9];
    const float* W1       = (const float*)d_in[10];
    const float* b1       = (const float*)d_in[11];
    const float* W2       = (const float*)d_in[12];
    const float* b2       = (const float*)d_in[13];
    float* out            = (float*)d_out;

    int N = in_sizes[0] / DIM;
    int E = in_sizes[1] / 2;
    int nb = (N + SCANB - 1) / SCANB;
    int mb = (N + 127) / 128;

    float *p_ln;
    __half *pw0, *pw1, *pw2, *p_lnh, *p_th;
    cudaGetSymbolAddress((void**)&p_ln, g_ln);
    cudaGetSymbolAddress((void**)&p_lnh, g_lnh);
    cudaGetSymbolAddress((void**)&p_th, g_th);
    cudaGetSymbolAddress((void**)&pw0, g_w0);
    cudaGetSymbolAddress((void**)&pw1, g_w1);
    cudaGetSymbolAddress((void**)&pw2, g_w2);

    cudaFuncSetAttribute((const void*)k_fmma<3, 0>, cudaFuncAttributeMaxDynamicSharedMemorySize, FMMA_SMEM);
    cudaFuncSetAttribute((const void*)k_fmma<1, 1>, cudaFuncAttributeMaxDynamicSharedMemorySize, FMMA_SMEM);
    cudaFuncSetAttribute((const void*)k_fmma<4, 1>, cudaFuncAttributeMaxDynamicSharedMemorySize, FMMA_SMEM);

    // fork: CSR build on side stream
    cudaStream_t s2;
    cudaEvent_t evA, evB;
    cudaStreamCreateWithFlags(&s2, cudaStreamNonBlocking);
    cudaEventCreateWithFlags(&evA, cudaEventDisableTiming);
    cudaEventCreateWithFlags(&evB, cudaEventDisableTiming);

    cudaEventRecord(evA, 0);
    cudaStreamWaitEvent(s2, evA, 0);

    k_init<<<(N + 255) / 256, 256, 0, s2>>>(N);
    k_edge0<<<(E + 255) / 256, 256, 0, s2>>>(ei, E);
    k_scan1<<<nb, 256, 0, s2>>>(N);
    k_scan3<<<nb, 256, 0, s2>>>(N, nb);
    k_scatter<<<(E + 255) / 256, 256, 0, s2>>>(ei, E);
    cudaEventRecord(evB, s2);

    // main: weight prep, then h = x @ W with fused attention dots
    k_prepW<<<(81920 + 255) / 256, 256>>>(W, W1, W2);
    k_fmma<3, 0><<<dim3(1, mb), 256, FMMA_SMEM>>>(N, DIM, x, pw0,
                                                  nullptr, nullptr, nullptr, nullptr,
                                                  att_src, att_dst);

    cudaStreamWaitEvent(0, evB, 0);

    k_aggsort<<<(N * 32 + 255) / 256, 256>>>(N, gat_bias);
    k_lap1<<<(N * 32 + 255) / 256, 256>>>(N);
    k_lap2<<<(N * 32 + 255) / 256, 256>>>(N, x, ln1s, ln1b, ln2s, ln2b);

    k_fmma<1, 1><<<dim3(2, mb), 256, FMMA_SMEM>>>(N, DIM, p_lnh, pw1,
                                                  b1, nullptr, nullptr, p_th,
                                                  nullptr, nullptr);
    k_fmma<4, 1><<<dim3(1, mb), 256, FMMA_SMEM>>>(N, 2 * DIM, p_th, pw2,
                                                  b2, p_ln, out, nullptr,
                                                  nullptr, nullptr);
}

// round 9
// speedup vs baseline: 4.2529x; 1.0046x over previous
#include <cuda_runtime.h>
#include <cuda_fp16.h>
#include <stdint.h>
#include <math.h>

#define MAXN 50000
#define MAXE 800000
#define DIM 128
#define NH 8
#define SCANB 1024
#define MAXBLK 64

// ---------------- scratch (static device globals; no allocation) ------------
__device__ __half g_hh[MAXN * DIM];      // h = x @ W (fp16)
__device__ float g_as[MAXN * NH];
__device__ float g_ad[MAXN * NH];
__device__ float g_agg[MAXN * DIM];      // GAT output y
__device__ float g_di[MAXN];
__device__ float g_p[MAXN];
__device__ float g_pq[MAXN];
__device__ float g_mean[MAXN];
__device__ float g_ln[MAXN * DIM];       // LN output fp32 (residual for gemm2)
__device__ __half g_lnh[MAXN * DIM];     // LN output fp16 (A of gemm1)
__device__ __half g_th[MAXN * 2 * DIM];  // GELU intermediate fp16 (A of gemm2)
__device__ int   g_indeg[MAXN];
__device__ int   g_outdeg[MAXN];
__device__ int   g_offi[MAXN];           // CSR offsets by dst (post-scatter: end offsets)
__device__ int   g_offo[MAXN];           // CSR offsets by src (post-scatter: end offsets)
__device__ int   g_ssrc[MAXE];
__device__ int   g_sdst[MAXE];
__device__ int   g_bsum_i[MAXBLK];
__device__ int   g_bsum_o[MAXBLK];
// fp16 transposed weights [n][k]
__device__ __half g_w0[128 * 128];
__device__ __half g_w1[256 * 128];
__device__ __half g_w2[128 * 256];

// ---------------- helpers ---------------------------------------------------
__device__ __forceinline__ uint32_t smem_u32(const void* p) {
    uint32_t a;
    asm("{ .reg .u64 t; cvta.to.shared.u64 t, %1; cvt.u32.u64 %0, t; }"
        : "=r"(a) : "l"(p));
    return a;
}
__device__ __forceinline__ void ldsm_x4(uint32_t& r0, uint32_t& r1, uint32_t& r2,
                                        uint32_t& r3, uint32_t addr) {
    asm volatile("ldmatrix.sync.aligned.m8n8.x4.shared.b16 {%0,%1,%2,%3}, [%4];"
                 : "=r"(r0), "=r"(r1), "=r"(r2), "=r"(r3) : "r"(addr));
}
__device__ __forceinline__ void mma16816(float* c, const uint32_t* a, uint32_t b0, uint32_t b1) {
    asm volatile(
        "mma.sync.aligned.m16n8k16.row.col.f32.f16.f16.f32 "
        "{%0,%1,%2,%3}, {%4,%5,%6,%7}, {%8,%9}, {%0,%1,%2,%3};"
        : "+f"(c[0]), "+f"(c[1]), "+f"(c[2]), "+f"(c[3])
        : "r"(a[0]), "r"(a[1]), "r"(a[2]), "r"(a[3]), "r"(b0), "r"(b1));
}
__device__ __forceinline__ void cp16(void* dst_smem, const void* src, bool pred) {
    unsigned d = (unsigned)__cvta_generic_to_shared(dst_smem);
    int sz = pred ? 16 : 0;
    asm volatile("cp.async.cg.shared.global [%0], [%1], 16, %2;\n" :: "r"(d), "l"(src), "r"(sz));
}
__device__ __forceinline__ void cp_commit() { asm volatile("cp.async.commit_group;\n"); }
template <int NW>
__device__ __forceinline__ void cp_wait() { asm volatile("cp.async.wait_group %0;\n" :: "n"(NW)); }

__device__ __forceinline__ float gelu_exact(float v) {
    return 0.5f * v * (1.0f + erff(v * 0.7071067811865476f));
}
__device__ __forceinline__ float warp_sum(float s) {
#pragma unroll
    for (int o = 16; o > 0; o >>= 1) s += __shfl_xor_sync(0xffffffffu, s, o);
    return s;
}
__device__ __forceinline__ uint32_t packh2(float a, float b) {
    __half2 h = __floats2half2_rn(a, b);
    return *(uint32_t*)&h;
}

// ---------------- weight prep: transpose + fp16 ------------------------------
__global__ void k_prepW(const float* __restrict__ W, const float* __restrict__ W1,
                        const float* __restrict__ W2) {
    int i = blockIdx.x * blockDim.x + threadIdx.x;
    if (i < 16384) {
        int n = i >> 7, k = i & 127;
        g_w0[i] = __float2half_rn(W[k * 128 + n]);
    } else if (i < 49152) {
        int j = i - 16384;
        int n = j >> 7, k = j & 127;
        g_w1[j] = __float2half_rn(W1[k * 256 + n]);
    } else if (i < 81920) {
        int j = i - 49152;
        int n = j >> 8, k = j & 255;
        g_w2[j] = __float2half_rn(W2[k * 128 + n]);
    }
}

// ---------------- init / histograms / scan / scatter ------------------------
__global__ void k_init(int N) {
    int i = blockIdx.x * blockDim.x + threadIdx.x;
    if (i < N) { g_indeg[i] = 0; g_outdeg[i] = 0; }
}
__global__ void k_edge0(const int* __restrict__ ei, int E) {
    int e = blockIdx.x * blockDim.x + threadIdx.x;
    if (e >= E) return;
    atomicAdd(&g_outdeg[ei[e]], 1);
    atomicAdd(&g_indeg[ei[E + e]], 1);
}
__global__ void k_scan1(int N) {
    __shared__ int smi[256], smo[256];
    int base = blockIdx.x * SCANB + threadIdx.x * 4;
    int ti = 0, to = 0;
#pragma unroll
    for (int j = 0; j < 4; j++)
        if (base + j < N) { ti += g_indeg[base + j]; to += g_outdeg[base + j]; }
    smi[threadIdx.x] = ti; smo[threadIdx.x] = to;
    __syncthreads();
    for (int o = 128; o > 0; o >>= 1) {
        if (threadIdx.x < o) { smi[threadIdx.x] += smi[threadIdx.x + o];
                               smo[threadIdx.x] += smo[threadIdx.x + o]; }
        __syncthreads();
    }
    if (threadIdx.x == 0) { g_bsum_i[blockIdx.x] = smi[0]; g_bsum_o[blockIdx.x] = smo[0]; }
}
__global__ void k_scan3(int N, int nb) {
    __shared__ int smi[256], smo[256];
    __shared__ int sbi[MAXBLK], sbo[MAXBLK];
    __shared__ int basei, baseo;
    int tid = threadIdx.x;
    if (tid < nb) { sbi[tid] = g_bsum_i[tid]; sbo[tid] = g_bsum_o[tid]; }
    __syncthreads();
    if (tid == 0) {
        int bi = 0, bo = 0;
        for (int b = 0; b < (int)blockIdx.x; b++) { bi += sbi[b]; bo += sbo[b]; }
        basei = bi; baseo = bo;
    }
    int base = blockIdx.x * SCANB + tid * 4;
    int vi[4] = {0,0,0,0}, vo[4] = {0,0,0,0};
#pragma unroll
    for (int j = 0; j < 4; j++)
        if (base + j < N) { vi[j] = g_indeg[base + j]; vo[j] = g_outdeg[base + j]; }
    int tsi = vi[0]+vi[1]+vi[2]+vi[3], tso = vo[0]+vo[1]+vo[2]+vo[3];
    smi[tid] = tsi; smo[tid] = tso;
    __syncthreads();
    for (int o = 1; o < 256; o <<= 1) {
        int a = (tid >= o) ? smi[tid - o] : 0;
        int b = (tid >= o) ? smo[tid - o] : 0;
        __syncthreads();
        smi[tid] += a; smo[tid] += b;
        __syncthreads();
    }
    int gi = basei + smi[tid] - tsi;
    int go = baseo + smo[tid] - tso;
#pragma unroll
    for (int j = 0; j < 4; j++) {
        if (base + j < N) { g_offi[base + j] = gi; g_offo[base + j] = go; }
        gi += vi[j]; go += vo[j];
    }
}
// dst-CSR scatter: atomicAdd directly on offsets (consumer subtracts indeg)
__global__ void k_scatter_dst(const int* __restrict__ ei, int E) {
    int e = blockIdx.x * blockDim.x + threadIdx.x;
    if (e >= E) return;
    int s = ei[e], d = ei[E + e];
    g_ssrc[atomicAdd(&g_offi[d], 1)] = s;
}
// src-CSR scatter: runs overlapped with aggsort
__global__ void k_scatter_src(const int* __restrict__ ei, int E) {
    int e = blockIdx.x * blockDim.x + threadIdx.x;
    if (e >= E) return;
    int s = ei[e], d = ei[E + e];
    g_sdst[atomicAdd(&g_offo[s], 1)] = d;
}

// ---------------- fp16 mma GEMM with ldmatrix --------------------------------
// Tile 128x128, K chunked by 128. 256 threads = 8 warps (4m x 2n), warp 32x64.
// A: [m][Ktot] fp32 (AHALF=0, convert at stage) or fp16 (AHALF=1, cp.async).
// B: [n][Ktot] fp16 (col-major for mma.row.col).
// ACT: 1 = bias+GELU -> fp16 Cout16 (stride 256)
//      3 = fp16 h store + fused attention dots
//      4 = bias + residual + row-L2-normalize -> fp32 Cout (stride 128)
#define SAH 136                       // half stride (272 B/row, ldmatrix conflict-free)
#define FMMA_SMEM (2 * 128 * SAH * 2) // A tile + B tile, fp16
#define ZS 132

template <int ACT, int AHALF>
__global__ __launch_bounds__(256) void k_fmma(
        int M, int Ktot,
        const void* __restrict__ Ain,
        const __half* __restrict__ B,
        const float* __restrict__ bias,
        const float* __restrict__ res,
        float* __restrict__ Cout,
        __half* __restrict__ Cout16,
        const float* __restrict__ asrc,
        const float* __restrict__ adst) {
    extern __shared__ __align__(16) char smem[];
    __half* sA = (__half*)smem;                  // 128 x SAH
    __half* sB = (__half*)smem + 128 * SAH;      // 128 x SAH
    uint32_t sA32 = smem_u32(sA), sB32 = smem_u32(sB);

    int tid = threadIdx.x, wid = tid >> 5, lane = tid & 31;
    int row0 = blockIdx.y * 128, col0 = blockIdx.x * 128;
    int wm = wid & 3, wn = wid >> 2;
    int t4r = lane >> 2, t4c = lane & 3;

    float acc[2][8][4];
#pragma unroll
    for (int mt = 0; mt < 2; mt++)
#pragma unroll
        for (int nt = 0; nt < 8; nt++)
#pragma unroll
            for (int i = 0; i < 4; i++) acc[mt][nt][i] = 0.f;

    int T = Ktot >> 7;
    for (int kc = 0; kc < T; kc++) {
        int k0 = kc << 7;
        if (kc > 0) __syncthreads();  // previous compute done before overwrite
        // B tile: 128 rows x 128 halves, cp.async
#pragma unroll
        for (int j = 0; j < 8; j++) {
            int idx = tid + j * 256;
            int n = idx >> 4, g = (idx & 15) << 3;
            cp16(&sB[n * SAH + g], &B[(size_t)(col0 + n) * Ktot + k0 + g], true);
        }
        // A tile
        if (AHALF) {
            const __half* Ah = (const __half*)Ain;
#pragma unroll
            for (int j = 0; j < 8; j++) {
                int idx = tid + j * 256;
                int r = idx >> 4, g = (idx & 15) << 3;
                cp16(&sA[r * SAH + g], &Ah[(size_t)(row0 + r) * Ktot + k0 + g],
                     row0 + r < M);
            }
            cp_commit();
            cp_wait<0>();
        } else {
            cp_commit();
            const float* Af = (const float*)Ain;
#pragma unroll
            for (int j = 0; j < 8; j++) {
                int idx = tid + j * 256;
                int r = idx >> 4, g = (idx & 15) << 3;
                uint4 o = {0, 0, 0, 0};
                if (row0 + r < M) {
                    const float* ap = &Af[(size_t)(row0 + r) * Ktot + k0 + g];
                    float4 v0 = *(const float4*)ap;
                    float4 v1 = *(const float4*)(ap + 4);
                    o.x = packh2(v0.x, v0.y);
                    o.y = packh2(v0.z, v0.w);
                    o.z = packh2(v1.x, v1.y);
                    o.w = packh2(v1.z, v1.w);
                }
                *(uint4*)&sA[r * SAH + g] = o;
            }
            cp_wait<0>();
        }
        __syncthreads();

        // compute: 8 k16 steps
#pragma unroll
        for (int kk = 0; kk < 128; kk += 16) {
            uint32_t af[2][4];
#pragma unroll
            for (int mt = 0; mt < 2; mt++) {
                int r = wm * 32 + mt * 16 + (lane & 15);
                uint32_t addr = sA32 + r * (SAH * 2) + kk * 2 + (lane >> 4) * 16;
                ldsm_x4(af[mt][0], af[mt][1], af[mt][2], af[mt][3], addr);
            }
            uint32_t bf[8][2];
#pragma unroll
            for (int nb = 0; nb < 4; nb++) {
                int n = wn * 64 + nb * 16 + (lane & 15);
                uint32_t addr = sB32 + n * (SAH * 2) + kk * 2 + (lane >> 4) * 16;
                uint32_t q0, q1, q2, q3;
                ldsm_x4(q0, q1, q2, q3, addr);
                bf[nb * 2][0] = q0; bf[nb * 2 + 1][0] = q1;
                bf[nb * 2][1] = q2; bf[nb * 2 + 1][1] = q3;
            }
#pragma unroll
            for (int mt = 0; mt < 2; mt++)
#pragma unroll
                for (int nt = 0; nt < 8; nt++)
                    mma16816(acc[mt][nt], af[mt], bf[nt][0], bf[nt][1]);
        }
    }

    // ---------------- epilogues ----------------
    if (ACT == 1) {
#pragma unroll
        for (int mt = 0; mt < 2; mt++)
#pragma unroll
            for (int nt = 0; nt < 8; nt++) {
                int c = col0 + wn * 64 + nt * 8 + 2 * t4c;
                float bb0 = bias[c], bb1 = bias[c + 1];
#pragma unroll
                for (int half = 0; half < 2; half++) {
                    int r = row0 + wm * 32 + mt * 16 + t4r + half * 8;
                    if (r >= M) continue;
                    uint32_t o = packh2(gelu_exact(acc[mt][nt][half * 2 + 0] + bb0),
                                        gelu_exact(acc[mt][nt][half * 2 + 1] + bb1));
                    *(uint32_t*)&Cout16[(size_t)r * 256 + c] = o;
                }
            }
    } else if (ACT == 3) {
        // fp16 h store + attention dots (col0 == 0)
#pragma unroll
        for (int mt = 0; mt < 2; mt++)
#pragma unroll
            for (int half = 0; half < 2; half++) {
                int r = row0 + wm * 32 + mt * 16 + t4r + half * 8;
                bool ok = r < M;
                float pa[4] = {0,0,0,0}, pd[4] = {0,0,0,0};
#pragma unroll
                for (int nt = 0; nt < 8; nt++) {
                    int c = wn * 64 + nt * 8 + 2 * t4c;
                    float v0 = acc[mt][nt][half * 2 + 0];
                    float v1 = acc[mt][nt][half * 2 + 1];
                    if (ok) *(uint32_t*)&g_hh[(size_t)r * DIM + c] = packh2(v0, v1);
                    int p = nt >> 1;
                    pa[p] += v0 * __ldg(&asrc[c]) + v1 * __ldg(&asrc[c + 1]);
                    pd[p] += v0 * __ldg(&adst[c]) + v1 * __ldg(&adst[c + 1]);
                }
#pragma unroll
                for (int p = 0; p < 4; p++) {
                    pa[p] += __shfl_xor_sync(0xffffffffu, pa[p], 1);
                    pa[p] += __shfl_xor_sync(0xffffffffu, pa[p], 2);
                    pd[p] += __shfl_xor_sync(0xffffffffu, pd[p], 1);
                    pd[p] += __shfl_xor_sync(0xffffffffu, pd[p], 2);
                }
                if (ok && t4c == 0) {
#pragma unroll
                    for (int p = 0; p < 4; p++) {
                        g_as[r * NH + wn * 4 + p] = pa[p];
                        g_ad[r * NH + wn * 4 + p] = pd[p];
                    }
                }
            }
    } else {  // ACT == 4: bias + residual + row-L2-normalize (col0 == 0)
        float* zs = (float*)smem;  // 128 x ZS floats
        __syncthreads();           // compute done; smem reusable
#pragma unroll
        for (int mt = 0; mt < 2; mt++)
#pragma unroll
            for (int nt = 0; nt < 8; nt++) {
                int c = wn * 64 + nt * 8 + 2 * t4c;
                float bb0 = bias[c], bb1 = bias[c + 1];
#pragma unroll
                for (int half = 0; half < 2; half++) {
                    int rl = wm * 32 + mt * 16 + t4r + half * 8;
                    int r = row0 + rl;
                    if (r >= M) continue;
                    float2 rv = *(const float2*)&res[(size_t)r * DIM + c];
                    zs[rl * ZS + c]     = acc[mt][nt][half * 2 + 0] + bb0 + rv.x;
                    zs[rl * ZS + c + 1] = acc[mt][nt][half * 2 + 1] + bb1 + rv.y;
                }
            }
        __syncthreads();
#pragma unroll
        for (int rr = 0; rr < 16; rr++) {
            int rl = wid * 16 + rr;
            int r = row0 + rl;
            if (r >= M) continue;
            float4 z = *(float4*)&zs[rl * ZS + lane * 4];
            float ss = warp_sum(z.x * z.x + z.y * z.y + z.z * z.z + z.w * z.w);
            float inv = 1.f / fmaxf(sqrtf(ss), 1e-12f);
            float4 o = {z.x * inv, z.y * inv, z.z * inv, z.w * inv};
            *(float4*)&Cout[(size_t)r * DIM + lane * 4] = o;
        }
    }
}

// ---------------- sorted aggregation: warp per dst node (fp16 h) ------------
__global__ void k_aggsort(int N, const float* __restrict__ gat_bias) {
    int gid = blockIdx.x * blockDim.x + threadIdx.x;
    int n = gid >> 5;
    if (n >= N) return;
    int lane = gid & 31;
    int h = lane >> 2;
    int cnt = g_indeg[n];
    int off = g_offi[n] - cnt;   // post-scatter offsets are region ends
    float ad = g_ad[n * 8 + h];

    float4 acc = make_float4(0.f, 0.f, 0.f, 0.f);
    float den = 0.f;

    int i = 0;
    for (; i + 4 <= cnt; i += 4) {
        int s0 = __ldg(&g_ssrc[off + i]);
        int s1 = __ldg(&g_ssrc[off + i + 1]);
        int s2 = __ldg(&g_ssrc[off + i + 2]);
        int s3 = __ldg(&g_ssrc[off + i + 3]);
        float as0 = __ldg(&g_as[s0 * 8 + h]);
        float as1 = __ldg(&g_as[s1 * 8 + h]);
        float as2 = __ldg(&g_as[s2 * 8 + h]);
        float as3 = __ldg(&g_as[s3 * 8 + h]);
        uint2 r0 = __ldg((const uint2*)&g_hh[(size_t)s0 * DIM + lane * 4]);
        uint2 r1 = __ldg((const uint2*)&g_hh[(size_t)s1 * DIM + lane * 4]);
        uint2 r2 = __ldg((const uint2*)&g_hh[(size_t)s2 * DIM + lane * 4]);
        uint2 r3 = __ldg((const uint2*)&g_hh[(size_t)s3 * DIM + lane * 4]);
        float v0 = as0 + ad; v0 = v0 > 0.f ? v0 : 0.2f * v0;
        float v1 = as1 + ad; v1 = v1 > 0.f ? v1 : 0.2f * v1;
        float v2 = as2 + ad; v2 = v2 > 0.f ? v2 : 0.2f * v2;
        float v3 = as3 + ad; v3 = v3 > 0.f ? v3 : 0.2f * v3;
        float w0 = (s0 == n) ? 0.f : __expf(v0);
        float w1 = (s1 == n) ? 0.f : __expf(v1);
        float w2 = (s2 == n) ? 0.f : __expf(v2);
        float w3 = (s3 == n) ? 0.f : __expf(v3);
        den += (w0 + w1) + (w2 + w3);
        float2 a0 = __half22float2(*(__half2*)&r0.x), b0 = __half22float2(*(__half2*)&r0.y);
        float2 a1 = __half22float2(*(__half2*)&r1.x), b1 = __half22float2(*(__half2*)&r1.y);
        float2 a2 = __half22float2(*(__half2*)&r2.x), b2 = __half22float2(*(__half2*)&r2.y);
        float2 a3 = __half22float2(*(__half2*)&r3.x), b3 = __half22float2(*(__half2*)&r3.y);
        acc.x += w0 * a0.x + w1 * a1.x + w2 * a2.x + w3 * a3.x;
        acc.y += w0 * a0.y + w1 * a1.y + w2 * a2.y + w3 * a3.y;
        acc.z += w0 * b0.x + w1 * b1.x + w2 * b2.x + w3 * b3.x;
        acc.w += w0 * b0.y + w1 * b1.y + w2 * b2.y + w3 * b3.y;
    }
    for (; i < cnt; i++) {
        int s0 = __ldg(&g_ssrc[off + i]);
        float as0 = __ldg(&g_as[s0 * 8 + h]);
        uint2 r0 = __ldg((const uint2*)&g_hh[(size_t)s0 * DIM + lane * 4]);
        float2 a0 = __half22float2(*(__half2*)&r0.x), b0 = __half22float2(*(__half2*)&r0.y);
        float v0 = as0 + ad; v0 = v0 > 0.f ? v0 : 0.2f * v0;
        float w0 = (s0 == n) ? 0.f : __expf(v0);
        den += w0;
        acc.x += w0 * a0.x; acc.y += w0 * a0.y;
        acc.z += w0 * b0.x; acc.w += w0 * b0.y;
    }

    // self loop
    float asn = g_as[n * 8 + h];
    float vs = asn + ad; vs = vs > 0.f ? vs : 0.2f * vs;
    float ws = __expf(vs);
    uint2 rn = __ldg((const uint2*)&g_hh[(size_t)n * DIM + lane * 4]);
    float2 hna = __half22float2(*(__half2*)&rn.x);
    float2 hnb = __half22float2(*(__half2*)&rn.y);
    den += ws;
    acc.x += ws * hna.x; acc.y += ws * hna.y;
    acc.z += ws * hnb.x; acc.w += ws * hnb.y;

    float inv = 1.f / (den + 1e-16f);
    float4 b = ((const float4*)gat_bias)[lane];
    float4 y;
    y.x = acc.x * inv + b.x;
    y.y = acc.y * inv + b.y;
    y.z = acc.z * inv + b.z;
    y.w = acc.w * inv + b.w;
    ((float4*)g_agg)[(size_t)n * 32 + lane] = y;

    float sum = warp_sum(y.x + y.y + y.z + y.w);
    if (lane == 0) {
        float di = rsqrtf((float)g_outdeg[n] + 1e-6f);
        g_di[n] = di;
        g_p[n] = di * sum * (1.f / 128.f);
    }
}

// ---------------- laplacian passes -------------------------------------------
__global__ void k_lap1(int N) {
    int gid = blockIdx.x * blockDim.x + threadIdx.x;
    int n = gid >> 5;
    if (n >= N) return;
    int lane = gid & 31;
    int cnt = g_outdeg[n];
    int off = g_offo[n] - cnt;
    float s = 0.f;
    for (int i = lane; i < cnt; i += 32)
        s += __ldg(&g_p[__ldg(&g_sdst[off + i])]);
    s = warp_sum(s);
    float di = g_di[n];
    float mean = di * s;
    float4 y = ((const float4*)g_agg)[(size_t)n * 32 + lane];
    float a0 = y.x - mean, a1 = y.y - mean, a2 = y.z - mean, a3 = y.w - mean;
    float ss = warp_sum(a0 * a0 + a1 * a1 + a2 * a2 + a3 * a3);
    if (lane == 0) {
        g_mean[n] = mean;
        g_pq[n] = di * ss * (1.f / 128.f);
    }
}

__global__ void k_lap2(int N, const float* __restrict__ x,
                       const float* __restrict__ s1, const float* __restrict__ b1,
                       const float* __restrict__ s2, const float* __restrict__ b2) {
    int gid = blockIdx.x * blockDim.x + threadIdx.x;
    int n = gid >> 5;
    if (n >= N) return;
    int lane = gid & 31;
    int cnt = g_outdeg[n];
    int off = g_offo[n] - cnt;
    float s = 0.f;
    for (int i = lane; i < cnt; i += 32)
        s += __ldg(&g_pq[__ldg(&g_sdst[off + i])]);
    s = warp_sum(s);
    float var = g_di[n] * s;
    float m = g_mean[n];
    float inv1 = 1.f / sqrtf(var + 1e-6f);

    float4 y = ((const float4*)g_agg)[(size_t)n * 32 + lane];
    float4 xv = ((const float4*)x)[(size_t)n * 32 + lane];
    float4 sc1 = ((const float4*)s1)[lane];
    float4 bb1 = ((const float4*)b1)[lane];
    float4 sc2 = ((const float4*)s2)[lane];
    float4 bb2 = ((const float4*)b2)[lane];
    float o0 = (y.x - m) * inv1 * sc1.x + bb1.x + xv.x;
    float o1 = (y.y - m) * inv1 * sc1.y + bb1.y + xv.y;
    float o2 = (y.z - m) * inv1 * sc1.z + bb1.z + xv.z;
    float o3 = (y.w - m) * inv1 * sc1.w + bb1.w + xv.w;
    float mu = warp_sum(o0 + o1 + o2 + o3) * (1.f / 128.f);
    float c0 = o0 - mu, c1 = o1 - mu, c2 = o2 - mu, c3 = o3 - mu;
    float vs = warp_sum(c0 * c0 + c1 * c1 + c2 * c2 + c3 * c3);
    float inv2 = rsqrtf(vs * (1.f / 128.f) + 1e-5f);
    float4 r;
    r.x = c0 * inv2 * sc2.x + bb2.x;
    r.y = c1 * inv2 * sc2.y + bb2.y;
    r.z = c2 * inv2 * sc2.z + bb2.z;
    r.w = c3 * inv2 * sc2.w + bb2.w;
    ((float4*)g_ln)[(size_t)n * 32 + lane] = r;
    uint2 ho;
    ho.x = packh2(r.x, r.y);
    ho.y = packh2(r.z, r.w);
    *(uint2*)&g_lnh[(size_t)n * DIM + lane * 4] = ho;
}

// ---------------- launch ----------------------------------------------------
extern "C" void kernel_launch(void* const* d_in, const int* in_sizes, int n_in,
                              void* d_out, int out_size) {
    const float* x        = (const float*)d_in[0];
    const int* ei         = (const int*)d_in[1];
    const float* W        = (const float*)d_in[2];
    const float* att_src  = (const float*)d_in[3];
    const float* att_dst  = (const float*)d_in[4];
    const float* gat_bias = (const float*)d_in[5];
    const float* ln1s     = (const float*)d_in[6];
    const float* ln1b     = (const float*)d_in[7];
    const float* ln2s     = (const float*)d_in[8];
    const float* ln2b     = (const float*)d_in[9];
    const float* W1       = (const float*)d_in[10];
    const float* b1       = (const float*)d_in[11];
    const float* W2       = (const float*)d_in[12];
    const float* b2       = (const float*)d_in[13];
    float* out            = (float*)d_out;

    int N = in_sizes[0] / DIM;
    int E = in_sizes[1] / 2;
    int nb = (N + SCANB - 1) / SCANB;
    int mb = (N + 127) / 128;

    float *p_ln;
    __half *pw0, *pw1, *pw2, *p_lnh, *p_th;
    cudaGetSymbolAddress((void**)&p_ln, g_ln);
    cudaGetSymbolAddress((void**)&p_lnh, g_lnh);
    cudaGetSymbolAddress((void**)&p_th, g_th);
    cudaGetSymbolAddress((void**)&pw0, g_w0);
    cudaGetSymbolAddress((void**)&pw1, g_w1);
    cudaGetSymbolAddress((void**)&pw2, g_w2);

    cudaFuncSetAttribute((const void*)k_fmma<3, 0>, cudaFuncAttributeMaxDynamicSharedMemorySize, FMMA_SMEM);
    cudaFuncSetAttribute((const void*)k_fmma<1, 1>, cudaFuncAttributeMaxDynamicSharedMemorySize, FMMA_SMEM);
    cudaFuncSetAttribute((const void*)k_fmma<4, 1>, cudaFuncAttributeMaxDynamicSharedMemorySize, FMMA_SMEM);

    // fork: CSR build on side stream
    cudaStream_t s2;
    cudaEvent_t evA, evB, evC;
    cudaStreamCreateWithFlags(&s2, cudaStreamNonBlocking);
    cudaEventCreateWithFlags(&evA, cudaEventDisableTiming);
    cudaEventCreateWithFlags(&evB, cudaEventDisableTiming);
    cudaEventCreateWithFlags(&evC, cudaEventDisableTiming);

    cudaEventRecord(evA, 0);
    cudaStreamWaitEvent(s2, evA, 0);

    k_init<<<(N + 255) / 256, 256, 0, s2>>>(N);
    k_edge0<<<(E + 255) / 256, 256, 0, s2>>>(ei, E);
    k_scan1<<<nb, 256, 0, s2>>>(N);
    k_scan3<<<nb, 256, 0, s2>>>(N, nb);
    k_scatter_dst<<<(E + 255) / 256, 256, 0, s2>>>(ei, E);
    cudaEventRecord(evB, s2);
    // src-CSR built while aggsort runs on main stream
    k_scatter_src<<<(E + 255) / 256, 256, 0, s2>>>(ei, E);
    cudaEventRecord(evC, s2);

    // main: weight prep, then h = x @ W with fused attention dots
    k_prepW<<<(81920 + 255) / 256, 256>>>(W, W1, W2);
    k_fmma<3, 0><<<dim3(1, mb), 256, FMMA_SMEM>>>(N, DIM, x, pw0,
                                                  nullptr, nullptr, nullptr, nullptr,
                                                  att_src, att_dst);

    cudaStreamWaitEvent(0, evB, 0);
    k_aggsort<<<(N * 32 + 255) / 256, 256>>>(N, gat_bias);

    cudaStreamWaitEvent(0, evC, 0);
    k_lap1<<<(N * 32 + 255) / 256, 256>>>(N);
    k_lap2<<<(N * 32 + 255) / 256, 256>>>(N, x, ln1s, ln1b, ln2s, ln2b);

    k_fmma<1, 1><<<dim3(2, mb), 256, FMMA_SMEM>>>(N, DIM, p_lnh, pw1,
                                                  b1, nullptr, nullptr, p_th,
                                                  nullptr, nullptr);
    k_fmma<4, 1><<<dim3(1, mb), 256, FMMA_SMEM>>>(N, 2 * DIM, p_th, pw2,
                                                  b2, p_ln, out, nullptr,
                                                  nullptr, nullptr);
}

// round 10
// speedup vs baseline: 4.3702x; 1.0276x over previous
#include <cuda_runtime.h>
#include <cuda_fp16.h>
#include <stdint.h>
#include <math.h>

#define MAXN 50000
#define MAXE 800000
#define DIM 128
#define NH 8
#define SCANB 1024
#define MAXBLK 64

// ---------------- scratch (static device globals; no allocation) ------------
__device__ __half g_hh[MAXN * DIM];      // h = x @ W (fp16)
__device__ float g_as[MAXN * NH];
__device__ float g_ad[MAXN * NH];
__device__ float g_agg[MAXN * DIM];      // GAT output y
__device__ float g_di[MAXN];
__device__ float g_p[MAXN];
__device__ float g_pq[MAXN];
__device__ float g_mean[MAXN];
__device__ float g_ln[MAXN * DIM];       // LN output fp32 (residual for gemm2)
__device__ __half g_lnh[MAXN * DIM];     // LN output fp16 (A of gemm1)
__device__ __half g_th[MAXN * 2 * DIM];  // GELU intermediate fp16 (A of gemm2)
__device__ int   g_indeg[MAXN];
__device__ int   g_outdeg[MAXN];
__device__ int   g_offi[MAXN];           // CSR offsets by dst (post-scatter: end offsets)
__device__ int   g_offo[MAXN];           // CSR offsets by src (post-scatter: end offsets)
__device__ int   g_ssrc[MAXE];
__device__ int   g_sdst[MAXE];
__device__ int   g_bsum_i[MAXBLK];
__device__ int   g_bsum_o[MAXBLK];
// fp16 transposed weights [n][k]
__device__ __half g_w0[128 * 128];
__device__ __half g_w1[256 * 128];
__device__ __half g_w2[128 * 256];

// ---------------- helpers ---------------------------------------------------
__device__ __forceinline__ uint32_t smem_u32(const void* p) {
    uint32_t a;
    asm("{ .reg .u64 t; cvta.to.shared.u64 t, %1; cvt.u32.u64 %0, t; }"
        : "=r"(a) : "l"(p));
    return a;
}
__device__ __forceinline__ void ldsm_x4(uint32_t& r0, uint32_t& r1, uint32_t& r2,
                                        uint32_t& r3, uint32_t addr) {
    asm volatile("ldmatrix.sync.aligned.m8n8.x4.shared.b16 {%0,%1,%2,%3}, [%4];"
                 : "=r"(r0), "=r"(r1), "=r"(r2), "=r"(r3) : "r"(addr));
}
__device__ __forceinline__ void mma16816(float* c, const uint32_t* a, uint32_t b0, uint32_t b1) {
    asm volatile(
        "mma.sync.aligned.m16n8k16.row.col.f32.f16.f16.f32 "
        "{%0,%1,%2,%3}, {%4,%5,%6,%7}, {%8,%9}, {%0,%1,%2,%3};"
        : "+f"(c[0]), "+f"(c[1]), "+f"(c[2]), "+f"(c[3])
        : "r"(a[0]), "r"(a[1]), "r"(a[2]), "r"(a[3]), "r"(b0), "r"(b1));
}
__device__ __forceinline__ void cp16(void* dst_smem, const void* src, bool pred) {
    unsigned d = (unsigned)__cvta_generic_to_shared(dst_smem);
    int sz = pred ? 16 : 0;
    asm volatile("cp.async.cg.shared.global [%0], [%1], 16, %2;\n" :: "r"(d), "l"(src), "r"(sz));
}
__device__ __forceinline__ void cp_commit() { asm volatile("cp.async.commit_group;\n"); }
template <int NW>
__device__ __forceinline__ void cp_wait() { asm volatile("cp.async.wait_group %0;\n" :: "n"(NW)); }

__device__ __forceinline__ float gelu_exact(float v) {
    return 0.5f * v * (1.0f + erff(v * 0.7071067811865476f));
}
__device__ __forceinline__ float warp_sum(float s) {
#pragma unroll
    for (int o = 16; o > 0; o >>= 1) s += __shfl_xor_sync(0xffffffffu, s, o);
    return s;
}
__device__ __forceinline__ uint32_t packh2(float a, float b) {
    __half2 h = __floats2half2_rn(a, b);
    return *(uint32_t*)&h;
}

// ---------------- weight prep: transpose + fp16 ------------------------------
__global__ void k_prepW(const float* __restrict__ W, const float* __restrict__ W1,
                        const float* __restrict__ W2) {
    int i = blockIdx.x * blockDim.x + threadIdx.x;
    if (i < 16384) {
        int n = i >> 7, k = i & 127;
        g_w0[i] = __float2half_rn(W[k * 128 + n]);
    } else if (i < 49152) {
        int j = i - 16384;
        int n = j >> 7, k = j & 127;
        g_w1[j] = __float2half_rn(W1[k * 256 + n]);
    } else if (i < 81920) {
        int j = i - 49152;
        int n = j >> 8, k = j & 255;
        g_w2[j] = __float2half_rn(W2[k * 128 + n]);
    }
}

// ---------------- init / histograms / scan / scatter ------------------------
__global__ void k_init(int N) {
    int i = blockIdx.x * blockDim.x + threadIdx.x;
    if (i < N) { g_indeg[i] = 0; g_outdeg[i] = 0; }
}
__global__ void k_edge0(const int* __restrict__ ei, int E) {
    int e = blockIdx.x * blockDim.x + threadIdx.x;
    if (e >= E) return;
    atomicAdd(&g_outdeg[ei[e]], 1);
    atomicAdd(&g_indeg[ei[E + e]], 1);
}
__global__ void k_scan1(int N) {
    __shared__ int smi[256], smo[256];
    int base = blockIdx.x * SCANB + threadIdx.x * 4;
    int ti = 0, to = 0;
#pragma unroll
    for (int j = 0; j < 4; j++)
        if (base + j < N) { ti += g_indeg[base + j]; to += g_outdeg[base + j]; }
    smi[threadIdx.x] = ti; smo[threadIdx.x] = to;
    __syncthreads();
    for (int o = 128; o > 0; o >>= 1) {
        if (threadIdx.x < o) { smi[threadIdx.x] += smi[threadIdx.x + o];
                               smo[threadIdx.x] += smo[threadIdx.x + o]; }
        __syncthreads();
    }
    if (threadIdx.x == 0) { g_bsum_i[blockIdx.x] = smi[0]; g_bsum_o[blockIdx.x] = smo[0]; }
}
__global__ void k_scan3(int N, int nb) {
    __shared__ int smi[256], smo[256];
    __shared__ int sbi[MAXBLK], sbo[MAXBLK];
    __shared__ int basei, baseo;
    int tid = threadIdx.x;
    if (tid < nb) { sbi[tid] = g_bsum_i[tid]; sbo[tid] = g_bsum_o[tid]; }
    __syncthreads();
    if (tid == 0) {
        int bi = 0, bo = 0;
        for (int b = 0; b < (int)blockIdx.x; b++) { bi += sbi[b]; bo += sbo[b]; }
        basei = bi; baseo = bo;
    }
    int base = blockIdx.x * SCANB + tid * 4;
    int vi[4] = {0,0,0,0}, vo[4] = {0,0,0,0};
#pragma unroll
    for (int j = 0; j < 4; j++)
        if (base + j < N) { vi[j] = g_indeg[base + j]; vo[j] = g_outdeg[base + j]; }
    int tsi = vi[0]+vi[1]+vi[2]+vi[3], tso = vo[0]+vo[1]+vo[2]+vo[3];
    smi[tid] = tsi; smo[tid] = tso;
    __syncthreads();
    for (int o = 1; o < 256; o <<= 1) {
        int a = (tid >= o) ? smi[tid - o] : 0;
        int b = (tid >= o) ? smo[tid - o] : 0;
        __syncthreads();
        smi[tid] += a; smo[tid] += b;
        __syncthreads();
    }
    int gi = basei + smi[tid] - tsi;
    int go = baseo + smo[tid] - tso;
#pragma unroll
    for (int j = 0; j < 4; j++) {
        if (base + j < N) { g_offi[base + j] = gi; g_offo[base + j] = go; }
        gi += vi[j]; go += vo[j];
    }
}
// dst-CSR scatter: atomicAdd directly on offsets (consumer subtracts indeg)
__global__ void k_scatter_dst(const int* __restrict__ ei, int E) {
    int e = blockIdx.x * blockDim.x + threadIdx.x;
    if (e >= E) return;
    int s = ei[e], d = ei[E + e];
    g_ssrc[atomicAdd(&g_offi[d], 1)] = s;
}
// src-CSR scatter: runs overlapped with aggsort
__global__ void k_scatter_src(const int* __restrict__ ei, int E) {
    int e = blockIdx.x * blockDim.x + threadIdx.x;
    if (e >= E) return;
    int s = ei[e], d = ei[E + e];
    g_sdst[atomicAdd(&g_offo[s], 1)] = d;
}

// ---------------- fp16 mma GEMM with ldmatrix --------------------------------
// Tile 128x128, K chunked by 128. 256 threads = 8 warps (4m x 2n), warp 32x64.
// A: [m][Ktot] fp32 (AHALF=0, convert at stage) or fp16 (AHALF=1, cp.async).
// B: [n][Ktot] fp16 (col-major for mma.row.col).
// ACT: 1 = bias+GELU -> fp16 Cout16 (stride 256)
//      3 = fp16 h store + fused attention dots
//      4 = bias + residual + row-L2-normalize -> fp32 Cout (stride 128)
#define SAH 136                       // half stride (272 B/row, ldmatrix conflict-free)
#define FMMA_SMEM (2 * 128 * SAH * 2) // A tile + B tile, fp16
#define ZS 132

template <int ACT, int AHALF>
__global__ __launch_bounds__(256) void k_fmma(
        int M, int Ktot,
        const void* __restrict__ Ain,
        const __half* __restrict__ B,
        const float* __restrict__ bias,
        const float* __restrict__ res,
        float* __restrict__ Cout,
        __half* __restrict__ Cout16,
        const float* __restrict__ asrc,
        const float* __restrict__ adst) {
    extern __shared__ __align__(16) char smem[];
    __half* sA = (__half*)smem;                  // 128 x SAH
    __half* sB = (__half*)smem + 128 * SAH;      // 128 x SAH
    uint32_t sA32 = smem_u32(sA), sB32 = smem_u32(sB);

    int tid = threadIdx.x, wid = tid >> 5, lane = tid & 31;
    int row0 = blockIdx.y * 128, col0 = blockIdx.x * 128;
    int wm = wid & 3, wn = wid >> 2;
    int t4r = lane >> 2, t4c = lane & 3;

    float acc[2][8][4];
#pragma unroll
    for (int mt = 0; mt < 2; mt++)
#pragma unroll
        for (int nt = 0; nt < 8; nt++)
#pragma unroll
            for (int i = 0; i < 4; i++) acc[mt][nt][i] = 0.f;

    int T = Ktot >> 7;
    for (int kc = 0; kc < T; kc++) {
        int k0 = kc << 7;
        if (kc > 0) __syncthreads();  // previous compute done before overwrite
        // B tile: 128 rows x 128 halves, cp.async
#pragma unroll
        for (int j = 0; j < 8; j++) {
            int idx = tid + j * 256;
            int n = idx >> 4, g = (idx & 15) << 3;
            cp16(&sB[n * SAH + g], &B[(size_t)(col0 + n) * Ktot + k0 + g], true);
        }
        // A tile
        if (AHALF) {
            const __half* Ah = (const __half*)Ain;
#pragma unroll
            for (int j = 0; j < 8; j++) {
                int idx = tid + j * 256;
                int r = idx >> 4, g = (idx & 15) << 3;
                cp16(&sA[r * SAH + g], &Ah[(size_t)(row0 + r) * Ktot + k0 + g],
                     row0 + r < M);
            }
            cp_commit();
            cp_wait<0>();
        } else {
            cp_commit();
            const float* Af = (const float*)Ain;
#pragma unroll
            for (int j = 0; j < 8; j++) {
                int idx = tid + j * 256;
                int r = idx >> 4, g = (idx & 15) << 3;
                uint4 o = {0, 0, 0, 0};
                if (row0 + r < M) {
                    const float* ap = &Af[(size_t)(row0 + r) * Ktot + k0 + g];
                    float4 v0 = *(const float4*)ap;
                    float4 v1 = *(const float4*)(ap + 4);
                    o.x = packh2(v0.x, v0.y);
                    o.y = packh2(v0.z, v0.w);
                    o.z = packh2(v1.x, v1.y);
                    o.w = packh2(v1.z, v1.w);
                }
                *(uint4*)&sA[r * SAH + g] = o;
            }
            cp_wait<0>();
        }
        __syncthreads();

        // compute: 8 k16 steps
#pragma unroll
        for (int kk = 0; kk < 128; kk += 16) {
            uint32_t af[2][4];
#pragma unroll
            for (int mt = 0; mt < 2; mt++) {
                int r = wm * 32 + mt * 16 + (lane & 15);
                uint32_t addr = sA32 + r * (SAH * 2) + kk * 2 + (lane >> 4) * 16;
                ldsm_x4(af[mt][0], af[mt][1], af[mt][2], af[mt][3], addr);
            }
            uint32_t bf[8][2];
#pragma unroll
            for (int nb = 0; nb < 4; nb++) {
                int n = wn * 64 + nb * 16 + (lane & 15);
                uint32_t addr = sB32 + n * (SAH * 2) + kk * 2 + (lane >> 4) * 16;
                uint32_t q0, q1, q2, q3;
                ldsm_x4(q0, q1, q2, q3, addr);
                bf[nb * 2][0] = q0; bf[nb * 2 + 1][0] = q1;
                bf[nb * 2][1] = q2; bf[nb * 2 + 1][1] = q3;
            }
#pragma unroll
            for (int mt = 0; mt < 2; mt++)
#pragma unroll
                for (int nt = 0; nt < 8; nt++)
                    mma16816(acc[mt][nt], af[mt], bf[nt][0], bf[nt][1]);
        }
    }

    // ---------------- epilogues ----------------
    if (ACT == 1) {
#pragma unroll
        for (int mt = 0; mt < 2; mt++)
#pragma unroll
            for (int nt = 0; nt < 8; nt++) {
                int c = col0 + wn * 64 + nt * 8 + 2 * t4c;
                float bb0 = bias[c], bb1 = bias[c + 1];
#pragma unroll
                for (int half = 0; half < 2; half++) {
                    int r = row0 + wm * 32 + mt * 16 + t4r + half * 8;
                    if (r >= M) continue;
                    uint32_t o = packh2(gelu_exact(acc[mt][nt][half * 2 + 0] + bb0),
                                        gelu_exact(acc[mt][nt][half * 2 + 1] + bb1));
                    *(uint32_t*)&Cout16[(size_t)r * 256 + c] = o;
                }
            }
    } else if (ACT == 3) {
        // fp16 h store + attention dots (col0 == 0)
#pragma unroll
        for (int mt = 0; mt < 2; mt++)
#pragma unroll
            for (int half = 0; half < 2; half++) {
                int r = row0 + wm * 32 + mt * 16 + t4r + half * 8;
                bool ok = r < M;
                float pa[4] = {0,0,0,0}, pd[4] = {0,0,0,0};
#pragma unroll
                for (int nt = 0; nt < 8; nt++) {
                    int c = wn * 64 + nt * 8 + 2 * t4c;
                    float v0 = acc[mt][nt][half * 2 + 0];
                    float v1 = acc[mt][nt][half * 2 + 1];
                    if (ok) *(uint32_t*)&g_hh[(size_t)r * DIM + c] = packh2(v0, v1);
                    int p = nt >> 1;
                    pa[p] += v0 * __ldg(&asrc[c]) + v1 * __ldg(&asrc[c + 1]);
                    pd[p] += v0 * __ldg(&adst[c]) + v1 * __ldg(&adst[c + 1]);
                }
#pragma unroll
                for (int p = 0; p < 4; p++) {
                    pa[p] += __shfl_xor_sync(0xffffffffu, pa[p], 1);
                    pa[p] += __shfl_xor_sync(0xffffffffu, pa[p], 2);
                    pd[p] += __shfl_xor_sync(0xffffffffu, pd[p], 1);
                    pd[p] += __shfl_xor_sync(0xffffffffu, pd[p], 2);
                }
                if (ok && t4c == 0) {
#pragma unroll
                    for (int p = 0; p < 4; p++) {
                        g_as[r * NH + wn * 4 + p] = pa[p];
                        g_ad[r * NH + wn * 4 + p] = pd[p];
                    }
                }
            }
    } else {  // ACT == 4: bias + residual + row-L2-normalize (col0 == 0)
        float* zs = (float*)smem;  // 128 x ZS floats
        __syncthreads();           // compute done; smem reusable
#pragma unroll
        for (int mt = 0; mt < 2; mt++)
#pragma unroll
            for (int nt = 0; nt < 8; nt++) {
                int c = wn * 64 + nt * 8 + 2 * t4c;
                float bb0 = bias[c], bb1 = bias[c + 1];
#pragma unroll
                for (int half = 0; half < 2; half++) {
                    int rl = wm * 32 + mt * 16 + t4r + half * 8;
                    int r = row0 + rl;
                    if (r >= M) continue;
                    float2 rv = *(const float2*)&res[(size_t)r * DIM + c];
                    zs[rl * ZS + c]     = acc[mt][nt][half * 2 + 0] + bb0 + rv.x;
                    zs[rl * ZS + c + 1] = acc[mt][nt][half * 2 + 1] + bb1 + rv.y;
                }
            }
        __syncthreads();
#pragma unroll
        for (int rr = 0; rr < 16; rr++) {
            int rl = wid * 16 + rr;
            int r = row0 + rl;
            if (r >= M) continue;
            float4 z = *(float4*)&zs[rl * ZS + lane * 4];
            float ss = warp_sum(z.x * z.x + z.y * z.y + z.z * z.z + z.w * z.w);
            float inv = 1.f / fmaxf(sqrtf(ss), 1e-12f);
            float4 o = {z.x * inv, z.y * inv, z.z * inv, z.w * inv};
            *(float4*)&Cout[(size_t)r * DIM + lane * 4] = o;
        }
    }
}

// ---------------- sorted aggregation v2: warp per dst, 2 edges in flight ----
// 16 lanes per edge, 16B loads. lane16 = lane&15 owns cols [lane16*8, +8);
// head = lane16>>1. Group 0 (lanes 0-15) takes even edges, group 1 odd.
__global__ void k_aggsort(int N, const float* __restrict__ gat_bias) {
    int gid = blockIdx.x * blockDim.x + threadIdx.x;
    int n = gid >> 5;
    if (n >= N) return;
    int lane = gid & 31;
    int lane16 = lane & 15, grp = lane >> 4;
    int h = lane16 >> 1;
    int cnt = g_indeg[n];
    int off = g_offi[n] - cnt;   // post-scatter offsets are region ends
    float ad = g_ad[n * 8 + h];

    float acc[8] = {0.f, 0.f, 0.f, 0.f, 0.f, 0.f, 0.f, 0.f};
    float den = 0.f;

    int i = grp;
    for (; i + 2 < cnt; i += 4) {
        int s0 = __ldg(&g_ssrc[off + i]);
        int s1 = __ldg(&g_ssrc[off + i + 2]);
        float as0 = __ldg(&g_as[s0 * 8 + h]);
        float as1 = __ldg(&g_as[s1 * 8 + h]);
        uint4 r0 = __ldg((const uint4*)&g_hh[(size_t)s0 * DIM + lane16 * 8]);
        uint4 r1 = __ldg((const uint4*)&g_hh[(size_t)s1 * DIM + lane16 * 8]);
        float v0 = as0 + ad; v0 = v0 > 0.f ? v0 : 0.2f * v0;
        float v1 = as1 + ad; v1 = v1 > 0.f ? v1 : 0.2f * v1;
        float w0 = (s0 == n) ? 0.f : __expf(v0);
        float w1 = (s1 == n) ? 0.f : __expf(v1);
        den += w0 + w1;
        float2 p0 = __half22float2(*(__half2*)&r0.x), q0 = __half22float2(*(__half2*)&r1.x);
        float2 p1 = __half22float2(*(__half2*)&r0.y), q1 = __half22float2(*(__half2*)&r1.y);
        float2 p2 = __half22float2(*(__half2*)&r0.z), q2 = __half22float2(*(__half2*)&r1.z);
        float2 p3 = __half22float2(*(__half2*)&r0.w), q3 = __half22float2(*(__half2*)&r1.w);
        acc[0] += w0 * p0.x + w1 * q0.x; acc[1] += w0 * p0.y + w1 * q0.y;
        acc[2] += w0 * p1.x + w1 * q1.x; acc[3] += w0 * p1.y + w1 * q1.y;
        acc[4] += w0 * p2.x + w1 * q2.x; acc[5] += w0 * p2.y + w1 * q2.y;
        acc[6] += w0 * p3.x + w1 * q3.x; acc[7] += w0 * p3.y + w1 * q3.y;
    }
    for (; i < cnt; i += 2) {
        int s0 = __ldg(&g_ssrc[off + i]);
        float as0 = __ldg(&g_as[s0 * 8 + h]);
        uint4 r0 = __ldg((const uint4*)&g_hh[(size_t)s0 * DIM + lane16 * 8]);
        float v0 = as0 + ad; v0 = v0 > 0.f ? v0 : 0.2f * v0;
        float w0 = (s0 == n) ? 0.f : __expf(v0);
        den += w0;
        float2 p0 = __half22float2(*(__half2*)&r0.x);
        float2 p1 = __half22float2(*(__half2*)&r0.y);
        float2 p2 = __half22float2(*(__half2*)&r0.z);
        float2 p3 = __half22float2(*(__half2*)&r0.w);
        acc[0] += w0 * p0.x; acc[1] += w0 * p0.y;
        acc[2] += w0 * p1.x; acc[3] += w0 * p1.y;
        acc[4] += w0 * p2.x; acc[5] += w0 * p2.y;
        acc[6] += w0 * p3.x; acc[7] += w0 * p3.y;
    }

    // merge even/odd groups (lanes l and l+16 hold the same columns)
    den += __shfl_xor_sync(0xffffffffu, den, 16);
#pragma unroll
    for (int j = 0; j < 8; j++) acc[j] += __shfl_xor_sync(0xffffffffu, acc[j], 16);

    // self loop (all lanes, post-merge; identical across the two groups)
    float asn = g_as[n * 8 + h];
    float vs = asn + ad; vs = vs > 0.f ? vs : 0.2f * vs;
    float ws = __expf(vs);
    uint4 rn = __ldg((const uint4*)&g_hh[(size_t)n * DIM + lane16 * 8]);
    {
        float2 p0 = __half22float2(*(__half2*)&rn.x);
        float2 p1 = __half22float2(*(__half2*)&rn.y);
        float2 p2 = __half22float2(*(__half2*)&rn.z);
        float2 p3 = __half22float2(*(__half2*)&rn.w);
        acc[0] += ws * p0.x; acc[1] += ws * p0.y;
        acc[2] += ws * p1.x; acc[3] += ws * p1.y;
        acc[4] += ws * p2.x; acc[5] += ws * p2.y;
        acc[6] += ws * p3.x; acc[7] += ws * p3.y;
    }
    den += ws;

    float inv = 1.f / (den + 1e-16f);
    float4 b0 = ((const float4*)gat_bias)[lane16 * 2];
    float4 b1 = ((const float4*)gat_bias)[lane16 * 2 + 1];
    float y[8];
    y[0] = acc[0] * inv + b0.x; y[1] = acc[1] * inv + b0.y;
    y[2] = acc[2] * inv + b0.z; y[3] = acc[3] * inv + b0.w;
    y[4] = acc[4] * inv + b1.x; y[5] = acc[5] * inv + b1.y;
    y[6] = acc[6] * inv + b1.z; y[7] = acc[7] * inv + b1.w;

    // store: lane writes float4 at col = lane16*8 + grp*4 (duplicated halves split)
    {
        int cb = lane16 * 8 + grp * 4;
        float4 o = {y[grp * 4 + 0], y[grp * 4 + 1], y[grp * 4 + 2], y[grp * 4 + 3]};
        *(float4*)&g_agg[(size_t)n * DIM + cb] = o;
    }

    float sum = y[0] + y[1] + y[2] + y[3] + y[4] + y[5] + y[6] + y[7];
    sum = warp_sum(sum) * 0.5f;  // each column counted twice (dup across groups)
    if (lane == 0) {
        float di = rsqrtf((float)g_outdeg[n] + 1e-6f);
        g_di[n] = di;
        g_p[n] = di * sum * (1.f / 128.f);
    }
}

// ---------------- laplacian passes -------------------------------------------
__global__ void k_lap1(int N) {
    int gid = blockIdx.x * blockDim.x + threadIdx.x;
    int n = gid >> 5;
    if (n >= N) return;
    int lane = gid & 31;
    int cnt = g_outdeg[n];
    int off = g_offo[n] - cnt;
    float s = 0.f;
    for (int i = lane; i < cnt; i += 32)
        s += __ldg(&g_p[__ldg(&g_sdst[off + i])]);
    s = warp_sum(s);
    float di = g_di[n];
    float mean = di * s;
    float4 y = ((const float4*)g_agg)[(size_t)n * 32 + lane];
    float a0 = y.x - mean, a1 = y.y - mean, a2 = y.z - mean, a3 = y.w - mean;
    float ss = warp_sum(a0 * a0 + a1 * a1 + a2 * a2 + a3 * a3);
    if (lane == 0) {
        g_mean[n] = mean;
        g_pq[n] = di * ss * (1.f / 128.f);
    }
}

__global__ void k_lap2(int N, const float* __restrict__ x,
                       const float* __restrict__ s1, const float* __restrict__ b1,
                       const float* __restrict__ s2, const float* __restrict__ b2) {
    int gid = blockIdx.x * blockDim.x + threadIdx.x;
    int n = gid >> 5;
    if (n >= N) return;
    int lane = gid & 31;
    int cnt = g_outdeg[n];
    int off = g_offo[n] - cnt;
    float s = 0.f;
    for (int i = lane; i < cnt; i += 32)
        s += __ldg(&g_pq[__ldg(&g_sdst[off + i])]);
    s = warp_sum(s);
    float var = g_di[n] * s;
    float m = g_mean[n];
    float inv1 = 1.f / sqrtf(var + 1e-6f);

    float4 y = ((const float4*)g_agg)[(size_t)n * 32 + lane];
    float4 xv = ((const float4*)x)[(size_t)n * 32 + lane];
    float4 sc1 = ((const float4*)s1)[lane];
    float4 bb1 = ((const float4*)b1)[lane];
    float4 sc2 = ((const float4*)s2)[lane];
    float4 bb2 = ((const float4*)b2)[lane];
    float o0 = (y.x - m) * inv1 * sc1.x + bb1.x + xv.x;
    float o1 = (y.y - m) * inv1 * sc1.y + bb1.y + xv.y;
    float o2 = (y.z - m) * inv1 * sc1.z + bb1.z + xv.z;
    float o3 = (y.w - m) * inv1 * sc1.w + bb1.w + xv.w;
    float mu = warp_sum(o0 + o1 + o2 + o3) * (1.f / 128.f);
    float c0 = o0 - mu, c1 = o1 - mu, c2 = o2 - mu, c3 = o3 - mu;
    float vs = warp_sum(c0 * c0 + c1 * c1 + c2 * c2 + c3 * c3);
    float inv2 = rsqrtf(vs * (1.f / 128.f) + 1e-5f);
    float4 r;
    r.x = c0 * inv2 * sc2.x + bb2.x;
    r.y = c1 * inv2 * sc2.y + bb2.y;
    r.z = c2 * inv2 * sc2.z + bb2.z;
    r.w = c3 * inv2 * sc2.w + bb2.w;
    ((float4*)g_ln)[(size_t)n * 32 + lane] = r;
    uint2 ho;
    ho.x = packh2(r.x, r.y);
    ho.y = packh2(r.z, r.w);
    *(uint2*)&g_lnh[(size_t)n * DIM + lane * 4] = ho;
}

// ---------------- launch ----------------------------------------------------
extern "C" void kernel_launch(void* const* d_in, const int* in_sizes, int n_in,
                              void* d_out, int out_size) {
    const float* x        = (const float*)d_in[0];
    const int* ei         = (const int*)d_in[1];
    const float* W        = (const float*)d_in[2];
    const float* att_src  = (const float*)d_in[3];
    const float* att_dst  = (const float*)d_in[4];
    const float* gat_bias = (const float*)d_in[5];
    const float* ln1s     = (const float*)d_in[6];
    const float* ln1b     = (const float*)d_in[7];
    const float* ln2s     = (const float*)d_in[8];
    const float* ln2b     = (const float*)d_in[9];
    const float* W1       = (const float*)d_in[10];
    const float* b1       = (const float*)d_in[11];
    const float* W2       = (const float*)d_in[12];
    const float* b2       = (const float*)d_in[13];
    float* out            = (float*)d_out;

    int N = in_sizes[0] / DIM;
    int E = in_sizes[1] / 2;
    int nb = (N + SCANB - 1) / SCANB;
    int mb = (N + 127) / 128;

    float *p_ln;
    __half *pw0, *pw1, *pw2, *p_lnh, *p_th;
    cudaGetSymbolAddress((void**)&p_ln, g_ln);
    cudaGetSymbolAddress((void**)&p_lnh, g_lnh);
    cudaGetSymbolAddress((void**)&p_th, g_th);
    cudaGetSymbolAddress((void**)&pw0, g_w0);
    cudaGetSymbolAddress((void**)&pw1, g_w1);
    cudaGetSymbolAddress((void**)&pw2, g_w2);

    cudaFuncSetAttribute((const void*)k_fmma<3, 0>, cudaFuncAttributeMaxDynamicSharedMemorySize, FMMA_SMEM);
    cudaFuncSetAttribute((const void*)k_fmma<1, 1>, cudaFuncAttributeMaxDynamicSharedMemorySize, FMMA_SMEM);
    cudaFuncSetAttribute((const void*)k_fmma<4, 1>, cudaFuncAttributeMaxDynamicSharedMemorySize, FMMA_SMEM);

    // fork: CSR build on side stream
    cudaStream_t s2;
    cudaEvent_t evA, evB, evC;
    cudaStreamCreateWithFlags(&s2, cudaStreamNonBlocking);
    cudaEventCreateWithFlags(&evA, cudaEventDisableTiming);
    cudaEventCreateWithFlags(&evB, cudaEventDisableTiming);
    cudaEventCreateWithFlags(&evC, cudaEventDisableTiming);

    cudaEventRecord(evA, 0);
    cudaStreamWaitEvent(s2, evA, 0);

    k_init<<<(N + 255) / 256, 256, 0, s2>>>(N);
    k_edge0<<<(E + 255) / 256, 256, 0, s2>>>(ei, E);
    k_scan1<<<nb, 256, 0, s2>>>(N);
    k_scan3<<<nb, 256, 0, s2>>>(N, nb);
    k_scatter_dst<<<(E + 255) / 256, 256, 0, s2>>>(ei, E);
    cudaEventRecord(evB, s2);
    // src-CSR built while aggsort runs on main stream
    k_scatter_src<<<(E + 255) / 256, 256, 0, s2>>>(ei, E);
    cudaEventRecord(evC, s2);

    // main: weight prep, then h = x @ W with fused attention dots
    k_prepW<<<(81920 + 255) / 256, 256>>>(W, W1, W2);
    k_fmma<3, 0><<<dim3(1, mb), 256, FMMA_SMEM>>>(N, DIM, x, pw0,
                                                  nullptr, nullptr, nullptr, nullptr,
                                                  att_src, att_dst);

    cudaStreamWaitEvent(0, evB, 0);
    k_aggsort<<<(N * 32 + 255) / 256, 256>>>(N, gat_bias);

    cudaStreamWaitEvent(0, evC, 0);
    k_lap1<<<(N * 32 + 255) / 256, 256>>>(N);
    k_lap2<<<(N * 32 + 255) / 256, 256>>>(N, x, ln1s, ln1b, ln2s, ln2b);

    k_fmma<1, 1><<<dim3(2, mb), 256, FMMA_SMEM>>>(N, DIM, p_lnh, pw1,
                                                  b1, nullptr, nullptr, p_th,
                                                  nullptr, nullptr);
    k_fmma<4, 1><<<dim3(1, mb), 256, FMMA_SMEM>>>(N, 2 * DIM, p_th, pw2,
                                                  b2, p_ln, out, nullptr,
                                                  nullptr, nullptr);
}